// round 12
// baseline (speedup 1.0000x reference)
#include <cuda_runtime.h>
#include <cuda_bf16.h>
#include <cstdint>
#include <math.h>

// ---------------- problem constants ----------------
constexpr int N_NODES = 50000;
constexpr int N0      = 30000;
constexpr int N_EDGES = 600000;
constexpr int NT      = 8;
constexpr int K_TOT   = 1152;          // 8*128 rel + 128 root
constexpr int KC      = 64;
constexpr int NCHUNK  = K_TOT / KC;    // 18
constexpr int TILES0  = 235;           // ceil(30000/128)
constexpr int TILES1  = 157;           // ceil(20000/128)
constexpr int NTILES  = TILES0 + TILES1;
constexpr int N_PAD   = NTILES * 128;  // 50176 padded rows
constexpr int SEG     = NT * N_NODES;  // 400000 CSR segments, key = t*N + d
constexpr int NBLK    = (SEG + 1023) / 1024;  // 391

// ---------------- device scratch ----------------
__device__ float g_h1r[(size_t)N_NODES * 128];     // relu(h1), 25.6 MB
__device__ int   g_cnt[SEG];
__device__ int   g_off[SEG + 1];
__device__ int   g_cur[SEG];
__device__ int   g_esrc[N_EDGES];
__device__ int   g_bsum[NBLK];
__device__ int   g_bpre[NBLK];
// A buffers: [N_PAD][1152] bf16 hi/lo. Zero-initialized at module load; entries for
// empty segments / padded rows are NEVER written and stay zero (deterministic).
__device__ __align__(16) __nv_bfloat16 g_aggh[(size_t)N_PAD * K_TOT];  // 115.6 MB
__device__ __align__(16) __nv_bfloat16 g_aggl[(size_t)N_PAD * K_TOT];  // 115.6 MB
__device__ __align__(16) __nv_bfloat16 g_B1h[2 * 128 * K_TOT];
__device__ __align__(16) __nv_bfloat16 g_B1l[2 * 128 * K_TOT];
__device__ __align__(16) __nv_bfloat16 g_B2h[2 * 40 * K_TOT];
__device__ __align__(16) __nv_bfloat16 g_B2l[2 * 40 * K_TOT];

// ---------------- helpers ----------------
__device__ __forceinline__ uint32_t smem_u32(const void* p) {
    uint32_t a;
    asm("{ .reg .u64 t; cvta.to.shared.u64 t, %1; cvt.u32.u64 %0, t; }" : "=r"(a) : "l"(p));
    return a;
}
__device__ __forceinline__ uint32_t pack_bf16x2(float a, float b) {
    __nv_bfloat162 t = __floats2bfloat162_rn(a, b);
    return *reinterpret_cast<uint32_t*>(&t);
}
__device__ __forceinline__ void cp16(uint32_t s, const void* g) {
    asm volatile("cp.async.cg.shared.global [%0], [%1], 16;" :: "r"(s), "l"(g));
}
__device__ __forceinline__ void cp_commit() {
    asm volatile("cp.async.commit_group;" ::: "memory");
}
template<int N>
__device__ __forceinline__ void cp_wait() {
    asm volatile("cp.async.wait_group %0;" :: "n"(N) : "memory");
}
__device__ __forceinline__ void ldsm_x4(uint32_t addr, uint32_t* r) {
    asm volatile("ldmatrix.sync.aligned.m8n8.x4.shared.b16 {%0,%1,%2,%3}, [%4];"
                 : "=r"(r[0]), "=r"(r[1]), "=r"(r[2]), "=r"(r[3]) : "r"(addr));
}
__device__ __forceinline__ void ldsm_x2(uint32_t addr, uint32_t* r) {
    asm volatile("ldmatrix.sync.aligned.m8n8.x2.shared.b16 {%0,%1}, [%2];"
                 : "=r"(r[0]), "=r"(r[1]) : "r"(addr));
}
__device__ __forceinline__ void mma_bf16(float* c, const uint32_t* a, uint32_t b0, uint32_t b1) {
    asm volatile(
        "mma.sync.aligned.m16n8k16.row.col.f32.bf16.bf16.f32 "
        "{%0,%1,%2,%3}, {%4,%5,%6,%7}, {%8,%9}, {%0,%1,%2,%3};"
        : "+f"(c[0]), "+f"(c[1]), "+f"(c[2]), "+f"(c[3])
        : "r"(a[0]), "r"(a[1]), "r"(a[2]), "r"(a[3]), "r"(b0), "r"(b1));
}

// ---------------- CSR build ----------------
__global__ void count_kernel(const int* __restrict__ dst, const int* __restrict__ et) {
    int e = blockIdx.x * blockDim.x + threadIdx.x;
    if (e < N_EDGES) atomicAdd(&g_cnt[et[e] * N_NODES + dst[e]], 1);
}

__global__ void scanA_kernel() {
    __shared__ int sm[256];
    int base = blockIdx.x * 1024 + threadIdx.x * 4;
    int s = 0;
#pragma unroll
    for (int j = 0; j < 4; j++) { int i = base + j; if (i < SEG) s += g_cnt[i]; }
    sm[threadIdx.x] = s; __syncthreads();
    for (int off = 128; off > 0; off >>= 1) {
        if (threadIdx.x < off) sm[threadIdx.x] += sm[threadIdx.x + off];
        __syncthreads();
    }
    if (threadIdx.x == 0) g_bsum[blockIdx.x] = sm[0];
}

__global__ void scanB_kernel() {
    __shared__ int sm[512];
    int tid = threadIdx.x;
    int v = (tid < NBLK) ? g_bsum[tid] : 0;
    sm[tid] = v; __syncthreads();
    for (int off = 1; off < 512; off <<= 1) {
        int t = (tid >= off) ? sm[tid - off] : 0;
        __syncthreads();
        sm[tid] += t;
        __syncthreads();
    }
    if (tid < NBLK) g_bpre[tid] = sm[tid] - v;
    if (tid == 0) g_off[SEG] = N_EDGES;
}

__global__ void scanC_kernel() {
    __shared__ int sm[256];
    int tid = threadIdx.x;
    int base = blockIdx.x * 1024 + tid * 4;
    int c[4]; int ls = 0;
#pragma unroll
    for (int j = 0; j < 4; j++) { int i = base + j; c[j] = (i < SEG) ? g_cnt[i] : 0; ls += c[j]; }
    sm[tid] = ls; __syncthreads();
    for (int off = 1; off < 256; off <<= 1) {
        int t = (tid >= off) ? sm[tid - off] : 0;
        __syncthreads();
        sm[tid] += t;
        __syncthreads();
    }
    int run = g_bpre[blockIdx.x] + sm[tid] - ls;
#pragma unroll
    for (int j = 0; j < 4; j++) {
        int i = base + j;
        if (i < SEG) {
            g_off[i] = run; g_cur[i] = run;
            run += c[j];
        }
    }
}

__global__ void scatter_kernel(const int* __restrict__ src, const int* __restrict__ dst,
                               const int* __restrict__ et) {
    int e = blockIdx.x * blockDim.x + threadIdx.x;
    if (e >= N_EDGES) return;
    int key = et[e] * N_NODES + dst[e];
    int pos = atomicAdd(&g_cur[key], 1);
    g_esrc[pos] = src[e];
}

// ---------------- aggregation + root fill (atomic-free, warp per unit) ----------------
// units [0,SEG): agg[d][t*128+c] = mean of source rows; EMPTY segments skipped —
//                their agg entries are never written and remain the loader's zeros.
// units [SEG,SEG+N): agg[n][1024+c] = own features (root block)
template<int SRC>
__global__ void agg_kernel(const float* __restrict__ R0, const float* __restrict__ R1)
{
    int w = (blockIdx.x * blockDim.x + threadIdx.x) >> 5;
    int lane = threadIdx.x & 31;
    if (w < SEG) {
        int o0 = g_off[w], o1 = g_off[w + 1];
        int len = o1 - o0;
        if (len == 0) return;                      // zeros persist from zero-init
        int t = w / N_NODES;
        int d = w - t * N_NODES;
        float4 acc = make_float4(0.f, 0.f, 0.f, 0.f);
        for (int e = o0; e < o1; e++) {
            int s = g_esrc[e];
            const float* xs = (SRC == 0)
                ? ((s < N0) ? R0 + (size_t)s * 128 : R1 + (size_t)(s - N0) * 128)
                : R0 + (size_t)s * 128;
            float4 v = reinterpret_cast<const float4*>(xs)[lane];
            acc.x += v.x; acc.y += v.y; acc.z += v.z; acc.w += v.w;
        }
        float inv = 1.0f / (float)len;
        acc.x *= inv; acc.y *= inv; acc.z *= inv; acc.w *= inv;
        uint2 hv, lv;
        hv.x = pack_bf16x2(acc.x, acc.y);
        hv.y = pack_bf16x2(acc.z, acc.w);
        lv.x = pack_bf16x2(acc.x - __bfloat162float(__float2bfloat16(acc.x)),
                           acc.y - __bfloat162float(__float2bfloat16(acc.y)));
        lv.y = pack_bf16x2(acc.z - __bfloat162float(__float2bfloat16(acc.z)),
                           acc.w - __bfloat162float(__float2bfloat16(acc.w)));
        size_t o = (size_t)d * K_TOT + t * 128 + lane * 4;
        *reinterpret_cast<uint2*>(g_aggh + o) = hv;
        *reinterpret_cast<uint2*>(g_aggl + o) = lv;
    } else if (w < SEG + N_NODES) {
        int d = w - SEG;
        const float* xs = (SRC == 0)
            ? ((d < N0) ? R0 + (size_t)d * 128 : R1 + (size_t)(d - N0) * 128)
            : R0 + (size_t)d * 128;
        float4 v = reinterpret_cast<const float4*>(xs)[lane];
        uint2 hv, lv;
        hv.x = pack_bf16x2(v.x, v.y);
        hv.y = pack_bf16x2(v.z, v.w);
        lv.x = pack_bf16x2(v.x - __bfloat162float(__float2bfloat16(v.x)),
                           v.y - __bfloat162float(__float2bfloat16(v.y)));
        lv.y = pack_bf16x2(v.z - __bfloat162float(__float2bfloat16(v.z)),
                           v.w - __bfloat162float(__float2bfloat16(v.w)));
        size_t o = (size_t)d * K_TOT + 1024 + lane * 4;
        *reinterpret_cast<uint2*>(g_aggh + o) = hv;
        *reinterpret_cast<uint2*>(g_aggl + o) = lv;
    }
}

// ---------------- B prep ----------------
template<int NB>
__global__ void prepB_kernel(const float* __restrict__ rel_w, const float* __restrict__ root_w,
                             __nv_bfloat16* __restrict__ Bh, __nv_bfloat16* __restrict__ Bl)
{
    int i = blockIdx.x * blockDim.x + threadIdx.x;
    if (i >= 2 * NB * K_TOT) return;
    int k = i % K_TOT;
    int n = (i / K_TOT) % NB;
    int v = i / (K_TOT * NB);
    float w = (k < NT * 128) ? rel_w[(k >> 7) * NB * 128 + n * 128 + (k & 127)]
                             : root_w[v * NB * 128 + n * 128 + (k - NT * 128)];
    __nv_bfloat16 h = __float2bfloat16(w);
    Bh[i] = h;
    Bl[i] = __float2bfloat16(w - __bfloat162float(h));
}

// ---------------- bf16x3 mma.sync GEMM with cp.async double buffering ----------------
// EPI 0: relu(D+bias) -> outp[row*128 + col], grid = dim3(NTILES, 2)
// EPI 1: log_softmax(D+bias) -> outp[row*40 + col], grid = dim3(NTILES, 1)
template<int BN, int EPI>
__global__ void __launch_bounds__(256, 2) gemm_kernel(
    const __nv_bfloat16* __restrict__ Bh, const __nv_bfloat16* __restrict__ Bl,
    const float* __restrict__ bias, float* __restrict__ outp)
{
    constexpr int NBT = (EPI == 0) ? 128 : 40;
    constexpr int WARPS_M = (BN == 64) ? 4 : 8;
    constexpr int WARPS_N = (BN == 64) ? 2 : 1;
    constexpr int WM = 128 / WARPS_M;          // 32 or 16
    constexpr int WN = BN / WARPS_N;           // 32 or 40
    constexpr int MF = WM / 16;                // 2 or 1
    constexpr int NF = WN / 8;                 // 4 or 5
    constexpr int A_BYTES = 128 * KC * 2;      // 16384
    constexpr int B_BYTES = BN * KC * 2;
    constexpr int STAGE = 2 * A_BYTES + 2 * B_BYTES;

    extern __shared__ char smem[];
    const uint32_t sbase = smem_u32(smem);

    const int tid  = threadIdx.x;
    const int wid  = tid >> 5;
    const int lane = tid & 31;
    const int warpM = wid % WARPS_M;
    const int warpN = wid / WARPS_M;

    const int tile  = blockIdx.x;
    const int nbase = blockIdx.y * BN;
    const int var = (tile < TILES0) ? 0 : 1;
    const int mrow0 = var ? (N0 + (tile - TILES0) * 128) : (tile * 128);
    const int row_end = var ? N_NODES : N0;
    const __nv_bfloat16* Bhv = Bh + (size_t)var * NBT * K_TOT;
    const __nv_bfloat16* Blv = Bl + (size_t)var * NBT * K_TOT;
    const float* biasv = bias + var * NBT;
    const size_t aggRow0 = (size_t)mrow0 * K_TOT;

    float acc[MF][NF][4];
#pragma unroll
    for (int i = 0; i < MF; i++)
#pragma unroll
        for (int j = 0; j < NF; j++)
#pragma unroll
            for (int q = 0; q < 4; q++) acc[i][j][q] = 0.f;

    // ---- cp.async issue for chunk c into stage c&1 ----
    auto issue = [&](int c) {
        uint32_t ust = sbase + (c & 1) * STAGE;
        // A: 2048 x 16B (hi then lo)
#pragma unroll
        for (int i = 0; i < 8; i++) {
            int idx = tid + i * 256;
            int isLo = idx >= 1024;
            int ii = idx & 1023;
            int row = ii >> 3, u = ii & 7;
            const __nv_bfloat16* gp = (isLo ? g_aggl : g_aggh)
                + aggRow0 + (size_t)row * K_TOT + c * KC + u * 8;
            cp16(ust + (isLo ? A_BYTES : 0) + row * 128 + ((u ^ (row & 7)) << 4), gp);
        }
        // B: 2*BN*8 x 16B
        constexpr int BITEMS = 2 * BN * 8;
#pragma unroll
        for (int j = 0; j < (BITEMS + 255) / 256; j++) {
            int idx = tid + j * 256;
            if ((BITEMS % 256 == 0) || idx < BITEMS) {
                int isLo = idx >= BN * 8;
                int ii = isLo ? idx - BN * 8 : idx;
                int n = ii >> 3, u = ii & 7;
                const __nv_bfloat16* gp = (isLo ? Blv : Bhv)
                    + (size_t)(nbase + n) * K_TOT + c * KC + u * 8;
                cp16(ust + 2 * A_BYTES + (isLo ? B_BYTES : 0) + n * 128 + ((u ^ (n & 7)) << 4), gp);
            }
        }
        cp_commit();
    };

    issue(0);
    for (int c = 0; c < NCHUNK; c++) {
        if (c + 1 < NCHUNK) { issue(c + 1); cp_wait<1>(); }
        else                { cp_wait<0>(); }
        __syncthreads();

        const uint32_t ust = sbase + (c & 1) * STAGE;
        const uint32_t uAh = ust, uAl = ust + A_BYTES;
        const uint32_t uBh = ust + 2 * A_BYTES, uBl = uBh + B_BYTES;

#pragma unroll
        for (int p = 0; p < 3; p++) {
            uint32_t aBase = (p == 2) ? uAl : uAh;
            uint32_t bBase = (p == 1) ? uBl : uBh;
#pragma unroll
            for (int ks = 0; ks < 4; ks++) {
                uint32_t a[MF][4];
#pragma unroll
                for (int mf = 0; mf < MF; mf++) {
                    int row = warpM * WM + mf * 16 + (lane & 15);
                    int u = 2 * ks + (lane >> 4);
                    ldsm_x4(aBase + row * 128 + ((u ^ (row & 7)) << 4), a[mf]);
                }
#pragma unroll
                for (int nfp = 0; nfp < NF / 2; nfp++) {
                    int nrow = warpN * WN + nfp * 16 + ((lane >> 4) * 8) + (lane & 7);
                    int u = 2 * ks + ((lane >> 3) & 1);
                    uint32_t b[4];
                    ldsm_x4(bBase + nrow * 128 + ((u ^ (nrow & 7)) << 4), b);
#pragma unroll
                    for (int mf = 0; mf < MF; mf++) {
                        mma_bf16(acc[mf][2 * nfp + 0], a[mf], b[0], b[1]);
                        mma_bf16(acc[mf][2 * nfp + 1], a[mf], b[2], b[3]);
                    }
                }
                if (NF & 1) {
                    int l = lane & 15;
                    int nrow = warpN * WN + (NF - 1) * 8 + (l & 7);
                    int u = 2 * ks + (l >> 3);
                    uint32_t b[2];
                    ldsm_x2(bBase + nrow * 128 + ((u ^ (nrow & 7)) << 4), b);
#pragma unroll
                    for (int mf = 0; mf < MF; mf++)
                        mma_bf16(acc[mf][NF - 1], a[mf], b[0], b[1]);
                }
            }
        }
        __syncthreads();
    }

    // ---- epilogue ----
    if (EPI == 0) {
#pragma unroll
        for (int mf = 0; mf < MF; mf++) {
#pragma unroll
            for (int nf = 0; nf < NF; nf++) {
                int col = nbase + warpN * WN + nf * 8 + (lane & 3) * 2;
                float b0 = biasv[col], b1 = biasv[col + 1];
                int r0 = mrow0 + warpM * WM + mf * 16 + (lane >> 2);
                if (r0 < row_end) {
                    float2 v = make_float2(fmaxf(acc[mf][nf][0] + b0, 0.f),
                                           fmaxf(acc[mf][nf][1] + b1, 0.f));
                    *reinterpret_cast<float2*>(outp + (size_t)r0 * 128 + col) = v;
                }
                int r1 = r0 + 8;
                if (r1 < row_end) {
                    float2 v = make_float2(fmaxf(acc[mf][nf][2] + b0, 0.f),
                                           fmaxf(acc[mf][nf][3] + b1, 0.f));
                    *reinterpret_cast<float2*>(outp + (size_t)r1 * 128 + col) = v;
                }
            }
        }
    } else {
#pragma unroll
        for (int h = 0; h < 2; h++) {
            int row = mrow0 + wid * 16 + (lane >> 2) + h * 8;
            float v[2 * NF];
            float m = -INFINITY;
#pragma unroll
            for (int f = 0; f < NF; f++) {
                int col = f * 8 + (lane & 3) * 2;
                v[2 * f + 0] = acc[0][f][2 * h + 0] + biasv[col];
                v[2 * f + 1] = acc[0][f][2 * h + 1] + biasv[col + 1];
                m = fmaxf(m, fmaxf(v[2 * f], v[2 * f + 1]));
            }
            m = fmaxf(m, __shfl_xor_sync(0xFFFFFFFFu, m, 1));
            m = fmaxf(m, __shfl_xor_sync(0xFFFFFFFFu, m, 2));
            float s = 0.f;
#pragma unroll
            for (int j = 0; j < 2 * NF; j++) s += expf(v[j] - m);
            s += __shfl_xor_sync(0xFFFFFFFFu, s, 1);
            s += __shfl_xor_sync(0xFFFFFFFFu, s, 2);
            float l = m + logf(s);
            if (row < row_end) {
#pragma unroll
                for (int f = 0; f < NF; f++) {
                    int col = f * 8 + (lane & 3) * 2;
                    float2 o = make_float2(v[2 * f] - l, v[2 * f + 1] - l);
                    *reinterpret_cast<float2*>(outp + (size_t)row * 40 + col) = o;
                }
            }
        }
    }
}

// ---------------- launch ----------------
extern "C" void kernel_launch(void* const* d_in, const int* in_sizes, int n_in,
                              void* d_out, int out_size)
{
    const float* x0      = (const float*)d_in[0];
    const float* emb1    = (const float*)d_in[1];
    const float* rel_w1  = (const float*)d_in[2];
    const float* root_w1 = (const float*)d_in[3];
    const float* root_b1 = (const float*)d_in[4];
    const float* rel_w2  = (const float*)d_in[5];
    const float* root_w2 = (const float*)d_in[6];
    const float* root_b2 = (const float*)d_in[7];
    const int*   eidx    = (const int*)d_in[8];
    const int*   etype   = (const int*)d_in[9];
    (void)in_sizes; (void)n_in; (void)out_size;

    const int* src = eidx;
    const int* dst = eidx + N_EDGES;
    float* out = (float*)d_out;

    void *p_cnt, *p_h1r, *p_B1h, *p_B1l, *p_B2h, *p_B2l;
    cudaGetSymbolAddress(&p_cnt, g_cnt);
    cudaGetSymbolAddress(&p_h1r, g_h1r);
    cudaGetSymbolAddress(&p_B1h, g_B1h);
    cudaGetSymbolAddress(&p_B1l, g_B1l);
    cudaGetSymbolAddress(&p_B2h, g_B2h);
    cudaGetSymbolAddress(&p_B2l, g_B2l);

    constexpr int SMEM1 = 2 * (2 * 128 * KC * 2 + 2 * 64 * KC * 2);  // 98304
    constexpr int SMEM2 = 2 * (2 * 128 * KC * 2 + 2 * 40 * KC * 2);  // 86016
    cudaFuncSetAttribute(gemm_kernel<64, 0>, cudaFuncAttributeMaxDynamicSharedMemorySize, SMEM1);
    cudaFuncSetAttribute(gemm_kernel<40, 1>, cudaFuncAttributeMaxDynamicSharedMemorySize, SMEM2);

    // B weight split (tiny)
    prepB_kernel<128><<<(2 * 128 * K_TOT + 255) / 256, 256>>>(
        rel_w1, root_w1, (__nv_bfloat16*)p_B1h, (__nv_bfloat16*)p_B1l);
    prepB_kernel<40><<<(2 * 40 * K_TOT + 255) / 256, 256>>>(
        rel_w2, root_w2, (__nv_bfloat16*)p_B2h, (__nv_bfloat16*)p_B2l);

    // CSR build: count -> scan -> scatter
    cudaMemsetAsync(p_cnt, 0, sizeof(int) * SEG);
    count_kernel<<<(N_EDGES + 255) / 256, 256>>>(dst, etype);
    scanA_kernel<<<NBLK, 256>>>();
    scanB_kernel<<<1, 512>>>();
    scanC_kernel<<<NBLK, 256>>>();
    scatter_kernel<<<(N_EDGES + 255) / 256, 256>>>(src, dst, etype);

    const int AGG_BLOCKS = ((SEG + N_NODES) * 32 + 255) / 256;

    // layer 1: aggregation (+root fill, empty segments skipped) + pipelined GEMM -> g_h1r
    agg_kernel<0><<<AGG_BLOCKS, 256>>>(x0, emb1);
    gemm_kernel<64, 0><<<dim3(NTILES, 2), 256, SMEM1>>>(
        (const __nv_bfloat16*)p_B1h, (const __nv_bfloat16*)p_B1l, root_b1, (float*)p_h1r);

    // layer 2: aggregation (empty segments skipped) + GEMM -> d_out
    agg_kernel<1><<<AGG_BLOCKS, 256>>>((const float*)p_h1r, nullptr);
    gemm_kernel<40, 1><<<dim3(NTILES, 1), 256, SMEM2>>>(
        (const __nv_bfloat16*)p_B2h, (const __nv_bfloat16*)p_B2l, root_b2, out);
}

// round 13
// speedup vs baseline: 1.0150x; 1.0150x over previous
#include <cuda_runtime.h>
#include <cuda_bf16.h>
#include <cstdint>
#include <math.h>

// ---------------- problem constants ----------------
constexpr int N_NODES = 50000;
constexpr int N0      = 30000;
constexpr int N_EDGES = 600000;
constexpr int NT      = 8;
constexpr int K_TOT   = 1152;          // 8*128 rel + 128 root
constexpr int KC      = 64;            // layer-2 chunk
constexpr int NCHUNK  = K_TOT / KC;    // 18
constexpr int KC1     = 32;            // layer-1 chunk
constexpr int NCH1    = K_TOT / KC1;   // 36
constexpr int TILES0  = 235;           // ceil(30000/128)
constexpr int TILES1  = 157;           // ceil(20000/128)
constexpr int NTILES  = TILES0 + TILES1;
constexpr int N_PAD   = NTILES * 128;  // 50176 padded rows
constexpr int SEG     = NT * N_NODES;  // 400000 CSR segments, key = t*N + d
constexpr int NBLK    = (SEG + 1023) / 1024;  // 391

// ---------------- device scratch ----------------
__device__ float g_h1r[(size_t)N_NODES * 128];     // relu(h1), 25.6 MB
__device__ int   g_cnt[SEG];
__device__ int   g_off[SEG + 1];
__device__ int   g_cur[SEG];
__device__ int   g_esrc[N_EDGES];
__device__ int   g_bsum[NBLK];
__device__ int   g_bpre[NBLK];
// A buffers: [N_PAD][1152] bf16 hi/lo; padded rows never written -> stay zero.
__device__ __align__(16) __nv_bfloat16 g_aggh[(size_t)N_PAD * K_TOT];  // 115.6 MB
__device__ __align__(16) __nv_bfloat16 g_aggl[(size_t)N_PAD * K_TOT];  // 115.6 MB
__device__ __align__(16) __nv_bfloat16 g_B1h[2 * 128 * K_TOT];
__device__ __align__(16) __nv_bfloat16 g_B1l[2 * 128 * K_TOT];
__device__ __align__(16) __nv_bfloat16 g_B2h[2 * 40 * K_TOT];
__device__ __align__(16) __nv_bfloat16 g_B2l[2 * 40 * K_TOT];

// ---------------- helpers ----------------
__device__ __forceinline__ uint32_t smem_u32(const void* p) {
    uint32_t a;
    asm("{ .reg .u64 t; cvta.to.shared.u64 t, %1; cvt.u32.u64 %0, t; }" : "=r"(a) : "l"(p));
    return a;
}
__device__ __forceinline__ uint32_t pack_bf16x2(float a, float b) {
    __nv_bfloat162 t = __floats2bfloat162_rn(a, b);
    return *reinterpret_cast<uint32_t*>(&t);
}
__device__ __forceinline__ void cp16(uint32_t s, const void* g) {
    asm volatile("cp.async.cg.shared.global [%0], [%1], 16;" :: "r"(s), "l"(g));
}
__device__ __forceinline__ void cp_commit() {
    asm volatile("cp.async.commit_group;" ::: "memory");
}
template<int N>
__device__ __forceinline__ void cp_wait() {
    asm volatile("cp.async.wait_group %0;" :: "n"(N) : "memory");
}
__device__ __forceinline__ void ldsm_x4(uint32_t addr, uint32_t* r) {
    asm volatile("ldmatrix.sync.aligned.m8n8.x4.shared.b16 {%0,%1,%2,%3}, [%4];"
                 : "=r"(r[0]), "=r"(r[1]), "=r"(r[2]), "=r"(r[3]) : "r"(addr));
}
__device__ __forceinline__ void ldsm_x2(uint32_t addr, uint32_t* r) {
    asm volatile("ldmatrix.sync.aligned.m8n8.x2.shared.b16 {%0,%1}, [%2];"
                 : "=r"(r[0]), "=r"(r[1]) : "r"(addr));
}
__device__ __forceinline__ void mma_bf16(float* c, const uint32_t* a, uint32_t b0, uint32_t b1) {
    asm volatile(
        "mma.sync.aligned.m16n8k16.row.col.f32.bf16.bf16.f32 "
        "{%0,%1,%2,%3}, {%4,%5,%6,%7}, {%8,%9}, {%0,%1,%2,%3};"
        : "+f"(c[0]), "+f"(c[1]), "+f"(c[2]), "+f"(c[3])
        : "r"(a[0]), "r"(a[1]), "r"(a[2]), "r"(a[3]), "r"(b0), "r"(b1));
}

// ---------------- CSR build ----------------
__global__ void count_kernel(const int* __restrict__ dst, const int* __restrict__ et) {
    int e = blockIdx.x * blockDim.x + threadIdx.x;
    if (e < N_EDGES) atomicAdd(&g_cnt[et[e] * N_NODES + dst[e]], 1);
}

__global__ void scanA_kernel() {
    __shared__ int sm[256];
    int base = blockIdx.x * 1024 + threadIdx.x * 4;
    int s = 0;
#pragma unroll
    for (int j = 0; j < 4; j++) { int i = base + j; if (i < SEG) s += g_cnt[i]; }
    sm[threadIdx.x] = s; __syncthreads();
    for (int off = 128; off > 0; off >>= 1) {
        if (threadIdx.x < off) sm[threadIdx.x] += sm[threadIdx.x + off];
        __syncthreads();
    }
    if (threadIdx.x == 0) g_bsum[blockIdx.x] = sm[0];
}

__global__ void scanB_kernel() {
    __shared__ int sm[512];
    int tid = threadIdx.x;
    int v = (tid < NBLK) ? g_bsum[tid] : 0;
    sm[tid] = v; __syncthreads();
    for (int off = 1; off < 512; off <<= 1) {
        int t = (tid >= off) ? sm[tid - off] : 0;
        __syncthreads();
        sm[tid] += t;
        __syncthreads();
    }
    if (tid < NBLK) g_bpre[tid] = sm[tid] - v;
    if (tid == 0) g_off[SEG] = N_EDGES;
}

__global__ void scanC_kernel() {
    __shared__ int sm[256];
    int tid = threadIdx.x;
    int base = blockIdx.x * 1024 + tid * 4;
    int c[4]; int ls = 0;
#pragma unroll
    for (int j = 0; j < 4; j++) { int i = base + j; c[j] = (i < SEG) ? g_cnt[i] : 0; ls += c[j]; }
    sm[tid] = ls; __syncthreads();
    for (int off = 1; off < 256; off <<= 1) {
        int t = (tid >= off) ? sm[tid - off] : 0;
        __syncthreads();
        sm[tid] += t;
        __syncthreads();
    }
    int run = g_bpre[blockIdx.x] + sm[tid] - ls;
#pragma unroll
    for (int j = 0; j < 4; j++) {
        int i = base + j;
        if (i < SEG) {
            g_off[i] = run; g_cur[i] = run;
            run += c[j];
        }
    }
}

__global__ void scatter_kernel(const int* __restrict__ src, const int* __restrict__ dst,
                               const int* __restrict__ et) {
    int e = blockIdx.x * blockDim.x + threadIdx.x;
    if (e >= N_EDGES) return;
    int key = et[e] * N_NODES + dst[e];
    int pos = atomicAdd(&g_cur[key], 1);
    g_esrc[pos] = src[e];
}

// ---------------- aggregation + root fill (atomic-free, warp per unit) ----------------
template<int SRC>
__global__ void agg_kernel(const float* __restrict__ R0, const float* __restrict__ R1)
{
    int w = (blockIdx.x * blockDim.x + threadIdx.x) >> 5;
    int lane = threadIdx.x & 31;
    if (w < SEG) {
        int t = w / N_NODES;
        int d = w - t * N_NODES;
        int o0 = g_off[w], o1 = g_off[w + 1];
        float4 acc = make_float4(0.f, 0.f, 0.f, 0.f);
        for (int e = o0; e < o1; e++) {
            int s = g_esrc[e];
            const float* xs = (SRC == 0)
                ? ((s < N0) ? R0 + (size_t)s * 128 : R1 + (size_t)(s - N0) * 128)
                : R0 + (size_t)s * 128;
            float4 v = reinterpret_cast<const float4*>(xs)[lane];
            acc.x += v.x; acc.y += v.y; acc.z += v.z; acc.w += v.w;
        }
        int len = o1 - o0;
        float inv = 1.0f / (float)(len < 1 ? 1 : len);
        acc.x *= inv; acc.y *= inv; acc.z *= inv; acc.w *= inv;
        uint2 hv, lv;
        hv.x = pack_bf16x2(acc.x, acc.y);
        hv.y = pack_bf16x2(acc.z, acc.w);
        lv.x = pack_bf16x2(acc.x - __bfloat162float(__float2bfloat16(acc.x)),
                           acc.y - __bfloat162float(__float2bfloat16(acc.y)));
        lv.y = pack_bf16x2(acc.z - __bfloat162float(__float2bfloat16(acc.z)),
                           acc.w - __bfloat162float(__float2bfloat16(acc.w)));
        size_t o = (size_t)d * K_TOT + t * 128 + lane * 4;
        *reinterpret_cast<uint2*>(g_aggh + o) = hv;
        *reinterpret_cast<uint2*>(g_aggl + o) = lv;
    } else if (w < SEG + N_NODES) {
        int d = w - SEG;
        const float* xs = (SRC == 0)
            ? ((d < N0) ? R0 + (size_t)d * 128 : R1 + (size_t)(d - N0) * 128)
            : R0 + (size_t)d * 128;
        float4 v = reinterpret_cast<const float4*>(xs)[lane];
        uint2 hv, lv;
        hv.x = pack_bf16x2(v.x, v.y);
        hv.y = pack_bf16x2(v.z, v.w);
        lv.x = pack_bf16x2(v.x - __bfloat162float(__float2bfloat16(v.x)),
                           v.y - __bfloat162float(__float2bfloat16(v.y)));
        lv.y = pack_bf16x2(v.z - __bfloat162float(__float2bfloat16(v.z)),
                           v.w - __bfloat162float(__float2bfloat16(v.w)));
        size_t o = (size_t)d * K_TOT + 1024 + lane * 4;
        *reinterpret_cast<uint2*>(g_aggh + o) = hv;
        *reinterpret_cast<uint2*>(g_aggl + o) = lv;
    }
}

// ---------------- B prep ----------------
template<int NB>
__global__ void prepB_kernel(const float* __restrict__ rel_w, const float* __restrict__ root_w,
                             __nv_bfloat16* __restrict__ Bh, __nv_bfloat16* __restrict__ Bl)
{
    int i = blockIdx.x * blockDim.x + threadIdx.x;
    if (i >= 2 * NB * K_TOT) return;
    int k = i % K_TOT;
    int n = (i / K_TOT) % NB;
    int v = i / (K_TOT * NB);
    float w = (k < NT * 128) ? rel_w[(k >> 7) * NB * 128 + n * 128 + (k & 127)]
                             : root_w[v * NB * 128 + n * 128 + (k - NT * 128)];
    __nv_bfloat16 h = __float2bfloat16(w);
    Bh[i] = h;
    Bl[i] = __float2bfloat16(w - __bfloat162float(h));
}

// ========== layer-1 GEMM: BN=128, KC1=32, pitch-80 smem, A read ONCE ==========
// 2 stages x 40KB = 80KB/CTA -> 2 CTAs/SM (16 warps). 3-pass bf16x3, relu+bias.
constexpr int PITCH1   = 80;                       // 5x16B units per row: conflict-free
constexpr int ABUF1    = 128 * PITCH1;             // 10240
constexpr int STAGE1   = 4 * ABUF1;                // Ah,Al,Bh,Bl = 40960
constexpr int SMEM_G1  = 2 * STAGE1;               // 81920

__global__ void __launch_bounds__(256, 2) gemm1_kernel(
    const __nv_bfloat16* __restrict__ Bh, const __nv_bfloat16* __restrict__ Bl,
    const float* __restrict__ bias, float* __restrict__ outp)
{
    constexpr int MF = 2, NF = 8;                  // WARPS_M=4 (WM=32), WARPS_N=2 (WN=64)
    extern __shared__ char smem[];
    const uint32_t sbase = smem_u32(smem);

    const int tid  = threadIdx.x;
    const int wid  = tid >> 5;
    const int lane = tid & 31;
    const int warpM = wid & 3;
    const int warpN = wid >> 2;

    const int tile = blockIdx.x;
    const int var = (tile < TILES0) ? 0 : 1;
    const int mrow0 = var ? (N0 + (tile - TILES0) * 128) : (tile * 128);
    const int row_end = var ? N_NODES : N0;
    const __nv_bfloat16* Bhv = Bh + (size_t)var * 128 * K_TOT;
    const __nv_bfloat16* Blv = Bl + (size_t)var * 128 * K_TOT;
    const float* biasv = bias + var * 128;
    const size_t aggRow0 = (size_t)mrow0 * K_TOT;

    float acc[MF][NF][4];
#pragma unroll
    for (int i = 0; i < MF; i++)
#pragma unroll
        for (int j = 0; j < NF; j++)
#pragma unroll
            for (int q = 0; q < 4; q++) acc[i][j][q] = 0.f;

    auto issue = [&](int c) {
        uint32_t ust = sbase + (c & 1) * STAGE1;
#pragma unroll
        for (int i = 0; i < 8; i++) {
            int idx = tid + i * 256;               // 0..2047
            if (idx < 1024) {                      // A (hi then lo): 2x512 units
                int isLo = idx >= 512;
                int ii = idx & 511;
                int row = ii >> 2, u = ii & 3;
                const __nv_bfloat16* gp = (isLo ? g_aggl : g_aggh)
                    + aggRow0 + (size_t)row * K_TOT + c * KC1 + u * 8;
                cp16(ust + (isLo ? ABUF1 : 0) + row * PITCH1 + u * 16, gp);
            } else {                               // B (hi then lo): 2x512 units
                int j = idx - 1024;
                int isLo = j >= 512;
                int jj = j & 511;
                int n = jj >> 2, u = jj & 3;
                const __nv_bfloat16* gp = (isLo ? Blv : Bhv)
                    + (size_t)n * K_TOT + c * KC1 + u * 8;
                cp16(ust + 2 * ABUF1 + (isLo ? ABUF1 : 0) + n * PITCH1 + u * 16, gp);
            }
        }
        cp_commit();
    };

    issue(0);
    for (int c = 0; c < NCH1; c++) {
        if (c + 1 < NCH1) { issue(c + 1); cp_wait<1>(); }
        else              { cp_wait<0>(); }
        __syncthreads();

        const uint32_t ust = sbase + (c & 1) * STAGE1;
        const uint32_t uAh = ust, uAl = ust + ABUF1;
        const uint32_t uBh = ust + 2 * ABUF1, uBl = uBh + ABUF1;

#pragma unroll
        for (int p = 0; p < 3; p++) {
            uint32_t aBase = (p == 2) ? uAl : uAh;
            uint32_t bBase = (p == 1) ? uBl : uBh;
#pragma unroll
            for (int ks = 0; ks < 2; ks++) {
                uint32_t a[MF][4];
#pragma unroll
                for (int mf = 0; mf < MF; mf++) {
                    int row = warpM * 32 + mf * 16 + (lane & 15);
                    int u = 2 * ks + (lane >> 4);
                    ldsm_x4(aBase + row * PITCH1 + u * 16, a[mf]);
                }
#pragma unroll
                for (int nfp = 0; nfp < NF / 2; nfp++) {
                    int nrow = warpN * 64 + nfp * 16 + ((lane >> 4) * 8) + (lane & 7);
                    int u = 2 * ks + ((lane >> 3) & 1);
                    uint32_t b[4];
                    ldsm_x4(bBase + nrow * PITCH1 + u * 16, b);
#pragma unroll
                    for (int mf = 0; mf < MF; mf++) {
                        mma_bf16(acc[mf][2 * nfp + 0], a[mf], b[0], b[1]);
                        mma_bf16(acc[mf][2 * nfp + 1], a[mf], b[2], b[3]);
                    }
                }
            }
        }
        __syncthreads();
    }

    // epilogue: relu(D + bias)
#pragma unroll
    for (int mf = 0; mf < MF; mf++) {
#pragma unroll
        for (int nf = 0; nf < NF; nf++) {
            int col = warpN * 64 + nf * 8 + (lane & 3) * 2;
            float b0 = biasv[col], b1 = biasv[col + 1];
            int r0 = mrow0 + warpM * 32 + mf * 16 + (lane >> 2);
            if (r0 < row_end) {
                float2 v = make_float2(fmaxf(acc[mf][nf][0] + b0, 0.f),
                                       fmaxf(acc[mf][nf][1] + b1, 0.f));
                *reinterpret_cast<float2*>(outp + (size_t)r0 * 128 + col) = v;
            }
            int r1 = r0 + 8;
            if (r1 < row_end) {
                float2 v = make_float2(fmaxf(acc[mf][nf][2] + b0, 0.f),
                                       fmaxf(acc[mf][nf][3] + b1, 0.f));
                *reinterpret_cast<float2*>(outp + (size_t)r1 * 128 + col) = v;
            }
        }
    }
}

// ========== layer-2 GEMM: R7 config (BN=40, KC=64, 2-stage, log_softmax) ==========
__global__ void __launch_bounds__(256, 2) gemm2_kernel(
    const __nv_bfloat16* __restrict__ Bh, const __nv_bfloat16* __restrict__ Bl,
    const float* __restrict__ bias, float* __restrict__ outp)
{
    constexpr int BN = 40, NBT = 40;
    constexpr int WM = 16, WN = 40;
    constexpr int MF = 1, NF = 5;
    constexpr int A_BYTES = 128 * KC * 2;      // 16384
    constexpr int B_BYTES = BN * KC * 2;       // 5120
    constexpr int STAGE = 2 * A_BYTES + 2 * B_BYTES;

    extern __shared__ char smem[];
    const uint32_t sbase = smem_u32(smem);

    const int tid  = threadIdx.x;
    const int wid  = tid >> 5;
    const int lane = tid & 31;
    const int warpM = wid;

    const int tile = blockIdx.x;
    const int var = (tile < TILES0) ? 0 : 1;
    const int mrow0 = var ? (N0 + (tile - TILES0) * 128) : (tile * 128);
    const int row_end = var ? N_NODES : N0;
    const __nv_bfloat16* Bhv = Bh + (size_t)var * NBT * K_TOT;
    const __nv_bfloat16* Blv = Bl + (size_t)var * NBT * K_TOT;
    const float* biasv = bias + var * NBT;
    const size_t aggRow0 = (size_t)mrow0 * K_TOT;

    float acc[MF][NF][4];
#pragma unroll
    for (int i = 0; i < MF; i++)
#pragma unroll
        for (int j = 0; j < NF; j++)
#pragma unroll
            for (int q = 0; q < 4; q++) acc[i][j][q] = 0.f;

    auto issue = [&](int c) {
        uint32_t ust = sbase + (c & 1) * STAGE;
#pragma unroll
        for (int i = 0; i < 8; i++) {
            int idx = tid + i * 256;
            int isLo = idx >= 1024;
            int ii = idx & 1023;
            int row = ii >> 3, u = ii & 7;
            const __nv_bfloat16* gp = (isLo ? g_aggl : g_aggh)
                + aggRow0 + (size_t)row * K_TOT + c * KC + u * 8;
            cp16(ust + (isLo ? A_BYTES : 0) + row * 128 + ((u ^ (row & 7)) << 4), gp);
        }
        constexpr int BITEMS = 2 * BN * 8;     // 640
#pragma unroll
        for (int j = 0; j < (BITEMS + 255) / 256; j++) {
            int idx = tid + j * 256;
            if (idx < BITEMS) {
                int isLo = idx >= BN * 8;
                int ii = isLo ? idx - BN * 8 : idx;
                int n = ii >> 3, u = ii & 7;
                const __nv_bfloat16* gp = (isLo ? Blv : Bhv)
                    + (size_t)n * K_TOT + c * KC + u * 8;
                cp16(ust + 2 * A_BYTES + (isLo ? B_BYTES : 0) + n * 128 + ((u ^ (n & 7)) << 4), gp);
            }
        }
        cp_commit();
    };

    issue(0);
    for (int c = 0; c < NCHUNK; c++) {
        if (c + 1 < NCHUNK) { issue(c + 1); cp_wait<1>(); }
        else                { cp_wait<0>(); }
        __syncthreads();

        const uint32_t ust = sbase + (c & 1) * STAGE;
        const uint32_t uAh = ust, uAl = ust + A_BYTES;
        const uint32_t uBh = ust + 2 * A_BYTES, uBl = uBh + B_BYTES;

#pragma unroll
        for (int p = 0; p < 3; p++) {
            uint32_t aBase = (p == 2) ? uAl : uAh;
            uint32_t bBase = (p == 1) ? uBl : uBh;
#pragma unroll
            for (int ks = 0; ks < 4; ks++) {
                uint32_t a[MF][4];
#pragma unroll
                for (int mf = 0; mf < MF; mf++) {
                    int row = warpM * WM + mf * 16 + (lane & 15);
                    int u = 2 * ks + (lane >> 4);
                    ldsm_x4(aBase + row * 128 + ((u ^ (row & 7)) << 4), a[mf]);
                }
#pragma unroll
                for (int nfp = 0; nfp < NF / 2; nfp++) {
                    int nrow = nfp * 16 + ((lane >> 4) * 8) + (lane & 7);
                    int u = 2 * ks + ((lane >> 3) & 1);
                    uint32_t b[4];
                    ldsm_x4(bBase + nrow * 128 + ((u ^ (nrow & 7)) << 4), b);
#pragma unroll
                    for (int mf = 0; mf < MF; mf++) {
                        mma_bf16(acc[mf][2 * nfp + 0], a[mf], b[0], b[1]);
                        mma_bf16(acc[mf][2 * nfp + 1], a[mf], b[2], b[3]);
                    }
                }
                {   // NF odd tail
                    int l = lane & 15;
                    int nrow = (NF - 1) * 8 + (l & 7);
                    int u = 2 * ks + (l >> 3);
                    uint32_t b[2];
                    ldsm_x2(bBase + nrow * 128 + ((u ^ (nrow & 7)) << 4), b);
#pragma unroll
                    for (int mf = 0; mf < MF; mf++)
                        mma_bf16(acc[mf][NF - 1], a[mf], b[0], b[1]);
                }
            }
        }
        __syncthreads();
    }

    // epilogue: log_softmax(D + bias)
#pragma unroll
    for (int h = 0; h < 2; h++) {
        int row = mrow0 + wid * 16 + (lane >> 2) + h * 8;
        float v[2 * NF];
        float m = -INFINITY;
#pragma unroll
        for (int f = 0; f < NF; f++) {
            int col = f * 8 + (lane & 3) * 2;
            v[2 * f + 0] = acc[0][f][2 * h + 0] + biasv[col];
            v[2 * f + 1] = acc[0][f][2 * h + 1] + biasv[col + 1];
            m = fmaxf(m, fmaxf(v[2 * f], v[2 * f + 1]));
        }
        m = fmaxf(m, __shfl_xor_sync(0xFFFFFFFFu, m, 1));
        m = fmaxf(m, __shfl_xor_sync(0xFFFFFFFFu, m, 2));
        float s = 0.f;
#pragma unroll
        for (int j = 0; j < 2 * NF; j++) s += expf(v[j] - m);
        s += __shfl_xor_sync(0xFFFFFFFFu, s, 1);
        s += __shfl_xor_sync(0xFFFFFFFFu, s, 2);
        float l = m + logf(s);
        if (row < row_end) {
#pragma unroll
            for (int f = 0; f < NF; f++) {
                int col = f * 8 + (lane & 3) * 2;
                float2 o = make_float2(v[2 * f] - l, v[2 * f + 1] - l);
                *reinterpret_cast<float2*>(outp + (size_t)row * 40 + col) = o;
            }
        }
    }
}

// ---------------- launch ----------------
extern "C" void kernel_launch(void* const* d_in, const int* in_sizes, int n_in,
                              void* d_out, int out_size)
{
    const float* x0      = (const float*)d_in[0];
    const float* emb1    = (const float*)d_in[1];
    const float* rel_w1  = (const float*)d_in[2];
    const float* root_w1 = (const float*)d_in[3];
    const float* root_b1 = (const float*)d_in[4];
    const float* rel_w2  = (const float*)d_in[5];
    const float* root_w2 = (const float*)d_in[6];
    const float* root_b2 = (const float*)d_in[7];
    const int*   eidx    = (const int*)d_in[8];
    const int*   etype   = (const int*)d_in[9];
    (void)in_sizes; (void)n_in; (void)out_size;

    const int* src = eidx;
    const int* dst = eidx + N_EDGES;
    float* out = (float*)d_out;

    void *p_cnt, *p_h1r, *p_B1h, *p_B1l, *p_B2h, *p_B2l;
    cudaGetSymbolAddress(&p_cnt, g_cnt);
    cudaGetSymbolAddress(&p_h1r, g_h1r);
    cudaGetSymbolAddress(&p_B1h, g_B1h);
    cudaGetSymbolAddress(&p_B1l, g_B1l);
    cudaGetSymbolAddress(&p_B2h, g_B2h);
    cudaGetSymbolAddress(&p_B2l, g_B2l);

    constexpr int SMEM2 = 2 * (2 * 128 * KC * 2 + 2 * 40 * KC * 2);  // 86016
    cudaFuncSetAttribute(gemm1_kernel, cudaFuncAttributeMaxDynamicSharedMemorySize, SMEM_G1);
    cudaFuncSetAttribute(gemm2_kernel, cudaFuncAttributeMaxDynamicSharedMemorySize, SMEM2);

    // B weight split (tiny)
    prepB_kernel<128><<<(2 * 128 * K_TOT + 255) / 256, 256>>>(
        rel_w1, root_w1, (__nv_bfloat16*)p_B1h, (__nv_bfloat16*)p_B1l);
    prepB_kernel<40><<<(2 * 40 * K_TOT + 255) / 256, 256>>>(
        rel_w2, root_w2, (__nv_bfloat16*)p_B2h, (__nv_bfloat16*)p_B2l);

    // CSR build: count -> scan -> scatter
    cudaMemsetAsync(p_cnt, 0, sizeof(int) * SEG);
    count_kernel<<<(N_EDGES + 255) / 256, 256>>>(dst, etype);
    scanA_kernel<<<NBLK, 256>>>();
    scanB_kernel<<<1, 512>>>();
    scanC_kernel<<<NBLK, 256>>>();
    scatter_kernel<<<(N_EDGES + 255) / 256, 256>>>(src, dst, etype);

    const int AGG_BLOCKS = ((SEG + N_NODES) * 32 + 255) / 256;

    // layer 1: aggregation (+root fill) + single-A-pass GEMM -> g_h1r
    agg_kernel<0><<<AGG_BLOCKS, 256>>>(x0, emb1);
    gemm1_kernel<<<NTILES, 256, SMEM_G1>>>(
        (const __nv_bfloat16*)p_B1h, (const __nv_bfloat16*)p_B1l, root_b1, (float*)p_h1r);

    // layer 2: aggregation (+root fill) + GEMM -> d_out
    agg_kernel<1><<<AGG_BLOCKS, 256>>>((const float*)p_h1r, nullptr);
    gemm2_kernel<<<NTILES, 256, SMEM2>>>(
        (const __nv_bfloat16*)p_B2h, (const __nv_bfloat16*)p_B2l, root_b2, out);
}

// round 14
// speedup vs baseline: 1.3921x; 1.3716x over previous
#include <cuda_runtime.h>
#include <cuda_fp16.h>
#include <cstdint>
#include <math.h>

// ---------------- problem constants ----------------
constexpr int N_NODES = 50000;
constexpr int N0      = 30000;
constexpr int N_EDGES = 600000;
constexpr int NT      = 8;
constexpr int K_TOT   = 1152;          // 8*128 rel + 128 root
constexpr int KC      = 64;
constexpr int NCHUNK  = K_TOT / KC;    // 18
constexpr int TILES0  = 235;           // ceil(30000/128)
constexpr int TILES1  = 157;           // ceil(20000/128)
constexpr int NTILES  = TILES0 + TILES1;
constexpr int N_PAD   = NTILES * 128;  // 50176 padded rows
constexpr int SEG     = NT * N_NODES;  // 400000 CSR segments, key = t*N + d
constexpr int NBLK    = (SEG + 1023) / 1024;  // 391

// ---------------- device scratch ----------------
__device__ float g_h1r[(size_t)N_NODES * 128];     // relu(h1), 25.6 MB
__device__ int   g_cnt[SEG];
__device__ int   g_off[SEG + 1];
__device__ int   g_cur[SEG];
__device__ int   g_esrc[N_EDGES];
__device__ int   g_bsum[NBLK];
__device__ int   g_bpre[NBLK];
// A buffer: [N_PAD][1152] single fp16; padded rows never written -> stay zero.
__device__ __align__(16) __half g_agg[(size_t)N_PAD * K_TOT];          // 115.6 MB
__device__ __align__(16) __half g_B1h[2 * 128 * K_TOT];
__device__ __align__(16) __half g_B1l[2 * 128 * K_TOT];
__device__ __align__(16) __half g_B2h[2 * 40 * K_TOT];
__device__ __align__(16) __half g_B2l[2 * 40 * K_TOT];

// ---------------- helpers ----------------
__device__ __forceinline__ uint32_t smem_u32(const void* p) {
    uint32_t a;
    asm("{ .reg .u64 t; cvta.to.shared.u64 t, %1; cvt.u32.u64 %0, t; }" : "=r"(a) : "l"(p));
    return a;
}
__device__ __forceinline__ uint32_t pack_h2(float a, float b) {
    __half2 t = __floats2half2_rn(a, b);
    return *reinterpret_cast<uint32_t*>(&t);
}
__device__ __forceinline__ void cp16(uint32_t s, const void* g) {
    asm volatile("cp.async.cg.shared.global [%0], [%1], 16;" :: "r"(s), "l"(g));
}
__device__ __forceinline__ void cp_commit() {
    asm volatile("cp.async.commit_group;" ::: "memory");
}
template<int N>
__device__ __forceinline__ void cp_wait() {
    asm volatile("cp.async.wait_group %0;" :: "n"(N) : "memory");
}
__device__ __forceinline__ void ldsm_x4(uint32_t addr, uint32_t* r) {
    asm volatile("ldmatrix.sync.aligned.m8n8.x4.shared.b16 {%0,%1,%2,%3}, [%4];"
                 : "=r"(r[0]), "=r"(r[1]), "=r"(r[2]), "=r"(r[3]) : "r"(addr));
}
__device__ __forceinline__ void ldsm_x2(uint32_t addr, uint32_t* r) {
    asm volatile("ldmatrix.sync.aligned.m8n8.x2.shared.b16 {%0,%1}, [%2];"
                 : "=r"(r[0]), "=r"(r[1]) : "r"(addr));
}
__device__ __forceinline__ void mma_f16(float* c, const uint32_t* a, uint32_t b0, uint32_t b1) {
    asm volatile(
        "mma.sync.aligned.m16n8k16.row.col.f32.f16.f16.f32 "
        "{%0,%1,%2,%3}, {%4,%5,%6,%7}, {%8,%9}, {%0,%1,%2,%3};"
        : "+f"(c[0]), "+f"(c[1]), "+f"(c[2]), "+f"(c[3])
        : "r"(a[0]), "r"(a[1]), "r"(a[2]), "r"(a[3]), "r"(b0), "r"(b1));
}

// ---------------- CSR build ----------------
__global__ void count_kernel(const int* __restrict__ dst, const int* __restrict__ et) {
    int e = blockIdx.x * blockDim.x + threadIdx.x;
    if (e < N_EDGES) atomicAdd(&g_cnt[et[e] * N_NODES + dst[e]], 1);
}

__global__ void scanA_kernel() {
    __shared__ int sm[256];
    int base = blockIdx.x * 1024 + threadIdx.x * 4;
    int s = 0;
#pragma unroll
    for (int j = 0; j < 4; j++) { int i = base + j; if (i < SEG) s += g_cnt[i]; }
    sm[threadIdx.x] = s; __syncthreads();
    for (int off = 128; off > 0; off >>= 1) {
        if (threadIdx.x < off) sm[threadIdx.x] += sm[threadIdx.x + off];
        __syncthreads();
    }
    if (threadIdx.x == 0) g_bsum[blockIdx.x] = sm[0];
}

__global__ void scanB_kernel() {
    __shared__ int sm[512];
    int tid = threadIdx.x;
    int v = (tid < NBLK) ? g_bsum[tid] : 0;
    sm[tid] = v; __syncthreads();
    for (int off = 1; off < 512; off <<= 1) {
        int t = (tid >= off) ? sm[tid - off] : 0;
        __syncthreads();
        sm[tid] += t;
        __syncthreads();
    }
    if (tid < NBLK) g_bpre[tid] = sm[tid] - v;
    if (tid == 0) g_off[SEG] = N_EDGES;
}

__global__ void scanC_kernel() {
    __shared__ int sm[256];
    int tid = threadIdx.x;
    int base = blockIdx.x * 1024 + tid * 4;
    int c[4]; int ls = 0;
#pragma unroll
    for (int j = 0; j < 4; j++) { int i = base + j; c[j] = (i < SEG) ? g_cnt[i] : 0; ls += c[j]; }
    sm[tid] = ls; __syncthreads();
    for (int off = 1; off < 256; off <<= 1) {
        int t = (tid >= off) ? sm[tid - off] : 0;
        __syncthreads();
        sm[tid] += t;
        __syncthreads();
    }
    int run = g_bpre[blockIdx.x] + sm[tid] - ls;
#pragma unroll
    for (int j = 0; j < 4; j++) {
        int i = base + j;
        if (i < SEG) {
            g_off[i] = run; g_cur[i] = run;
            run += c[j];
        }
    }
}

__global__ void scatter_kernel(const int* __restrict__ src, const int* __restrict__ dst,
                               const int* __restrict__ et) {
    int e = blockIdx.x * blockDim.x + threadIdx.x;
    if (e >= N_EDGES) return;
    int key = et[e] * N_NODES + dst[e];
    int pos = atomicAdd(&g_cur[key], 1);
    g_esrc[pos] = src[e];
}

// ---------------- aggregation + root fill (atomic-free, warp per unit) ----------------
// units [0,SEG): agg[d][t*128+c] = mean of source rows (zeros if empty)
// units [SEG,SEG+N): agg[n][1024+c] = own features (root block)
// Output stored as single fp16.
template<int SRC>
__global__ void agg_kernel(const float* __restrict__ R0, const float* __restrict__ R1)
{
    int w = (blockIdx.x * blockDim.x + threadIdx.x) >> 5;
    int lane = threadIdx.x & 31;
    if (w < SEG) {
        int t = w / N_NODES;
        int d = w - t * N_NODES;
        int o0 = g_off[w], o1 = g_off[w + 1];
        float4 acc = make_float4(0.f, 0.f, 0.f, 0.f);
        for (int e = o0; e < o1; e++) {
            int s = g_esrc[e];
            const float* xs = (SRC == 0)
                ? ((s < N0) ? R0 + (size_t)s * 128 : R1 + (size_t)(s - N0) * 128)
                : R0 + (size_t)s * 128;
            float4 v = reinterpret_cast<const float4*>(xs)[lane];
            acc.x += v.x; acc.y += v.y; acc.z += v.z; acc.w += v.w;
        }
        int len = o1 - o0;
        float inv = 1.0f / (float)(len < 1 ? 1 : len);
        uint2 hv;
        hv.x = pack_h2(acc.x * inv, acc.y * inv);
        hv.y = pack_h2(acc.z * inv, acc.w * inv);
        *reinterpret_cast<uint2*>(g_agg + (size_t)d * K_TOT + t * 128 + lane * 4) = hv;
    } else if (w < SEG + N_NODES) {
        int d = w - SEG;
        const float* xs = (SRC == 0)
            ? ((d < N0) ? R0 + (size_t)d * 128 : R1 + (size_t)(d - N0) * 128)
            : R0 + (size_t)d * 128;
        float4 v = reinterpret_cast<const float4*>(xs)[lane];
        uint2 hv;
        hv.x = pack_h2(v.x, v.y);
        hv.y = pack_h2(v.z, v.w);
        *reinterpret_cast<uint2*>(g_agg + (size_t)d * K_TOT + 1024 + lane * 4) = hv;
    }
}

// ---------------- B prep: fp16 hi/lo split ----------------
template<int NB>
__global__ void prepB_kernel(const float* __restrict__ rel_w, const float* __restrict__ root_w,
                             __half* __restrict__ Bh, __half* __restrict__ Bl)
{
    int i = blockIdx.x * blockDim.x + threadIdx.x;
    if (i >= 2 * NB * K_TOT) return;
    int k = i % K_TOT;
    int n = (i / K_TOT) % NB;
    int v = i / (K_TOT * NB);
    float w = (k < NT * 128) ? rel_w[(k >> 7) * NB * 128 + n * 128 + (k & 127)]
                             : root_w[v * NB * 128 + n * 128 + (k - NT * 128)];
    __half h = __float2half_rn(w);
    Bh[i] = h;
    Bl[i] = __float2half_rn(w - __half2float(h));
}

// ---------------- fp16 mma.sync GEMM with cp.async double buffering ----------------
// 2 passes: A*Bh + A*Bl (A single fp16, B fp16 hi/lo).
// EPI 0: relu(D+bias) -> outp[row*128 + col], grid = dim3(NTILES, 2)
// EPI 1: log_softmax(D+bias) -> outp[row*40 + col], grid = dim3(NTILES, 1)
template<int BN, int EPI>
__global__ void __launch_bounds__(256, 2) gemm_kernel(
    const __half* __restrict__ Bh, const __half* __restrict__ Bl,
    const float* __restrict__ bias, float* __restrict__ outp)
{
    constexpr int NBT = (EPI == 0) ? 128 : 40;
    constexpr int WARPS_M = (BN == 64) ? 4 : 8;
    constexpr int WARPS_N = (BN == 64) ? 2 : 1;
    constexpr int WM = 128 / WARPS_M;          // 32 or 16
    constexpr int WN = BN / WARPS_N;           // 32 or 40
    constexpr int MF = WM / 16;                // 2 or 1
    constexpr int NF = WN / 8;                 // 4 or 5
    constexpr int A_BYTES = 128 * KC * 2;      // 16384 (single fp16 buffer)
    constexpr int B_BYTES = BN * KC * 2;
    constexpr int STAGE = A_BYTES + 2 * B_BYTES;

    extern __shared__ char smem[];
    const uint32_t sbase = smem_u32(smem);

    const int tid  = threadIdx.x;
    const int wid  = tid >> 5;
    const int lane = tid & 31;
    const int warpM = wid % WARPS_M;
    const int warpN = wid / WARPS_M;

    const int tile  = blockIdx.x;
    const int nbase = blockIdx.y * BN;
    const int var = (tile < TILES0) ? 0 : 1;
    const int mrow0 = var ? (N0 + (tile - TILES0) * 128) : (tile * 128);
    const int row_end = var ? N_NODES : N0;
    const __half* Bhv = Bh + (size_t)var * NBT * K_TOT;
    const __half* Blv = Bl + (size_t)var * NBT * K_TOT;
    const float* biasv = bias + var * NBT;
    const size_t aggRow0 = (size_t)mrow0 * K_TOT;

    float acc[MF][NF][4];
#pragma unroll
    for (int i = 0; i < MF; i++)
#pragma unroll
        for (int j = 0; j < NF; j++)
#pragma unroll
            for (int q = 0; q < 4; q++) acc[i][j][q] = 0.f;

    // ---- cp.async issue for chunk c into stage c&1 ----
    auto issue = [&](int c) {
        uint32_t ust = sbase + (c & 1) * STAGE;
        // A: 1024 x 16B
#pragma unroll
        for (int i = 0; i < 4; i++) {
            int idx = tid + i * 256;               // 0..1023
            int row = idx >> 3, u = idx & 7;
            const __half* gp = g_agg + aggRow0 + (size_t)row * K_TOT + c * KC + u * 8;
            cp16(ust + row * 128 + ((u ^ (row & 7)) << 4), gp);
        }
        // B: 2*BN*8 x 16B (hi then lo)
        constexpr int BITEMS = 2 * BN * 8;
#pragma unroll
        for (int j = 0; j < (BITEMS + 255) / 256; j++) {
            int idx = tid + j * 256;
            if ((BITEMS % 256 == 0) || idx < BITEMS) {
                int isLo = idx >= BN * 8;
                int ii = isLo ? idx - BN * 8 : idx;
                int n = ii >> 3, u = ii & 7;
                const __half* gp = (isLo ? Blv : Bhv)
                    + (size_t)(nbase + n) * K_TOT + c * KC + u * 8;
                cp16(ust + A_BYTES + (isLo ? B_BYTES : 0) + n * 128 + ((u ^ (n & 7)) << 4), gp);
            }
        }
        cp_commit();
    };

    issue(0);
    for (int c = 0; c < NCHUNK; c++) {
        if (c + 1 < NCHUNK) { issue(c + 1); cp_wait<1>(); }
        else                { cp_wait<0>(); }
        __syncthreads();

        const uint32_t ust = sbase + (c & 1) * STAGE;
        const uint32_t uA  = ust;
        const uint32_t uBh = ust + A_BYTES, uBl = uBh + B_BYTES;

#pragma unroll
        for (int p = 0; p < 2; p++) {
            uint32_t bBase = p ? uBl : uBh;
#pragma unroll
            for (int ks = 0; ks < 4; ks++) {
                uint32_t a[MF][4];
#pragma unroll
                for (int mf = 0; mf < MF; mf++) {
                    int row = warpM * WM + mf * 16 + (lane & 15);
                    int u = 2 * ks + (lane >> 4);
                    ldsm_x4(uA + row * 128 + ((u ^ (row & 7)) << 4), a[mf]);
                }
#pragma unroll
                for (int nfp = 0; nfp < NF / 2; nfp++) {
                    int nrow = warpN * WN + nfp * 16 + ((lane >> 4) * 8) + (lane & 7);
                    int u = 2 * ks + ((lane >> 3) & 1);
                    uint32_t b[4];
                    ldsm_x4(bBase + nrow * 128 + ((u ^ (nrow & 7)) << 4), b);
#pragma unroll
                    for (int mf = 0; mf < MF; mf++) {
                        mma_f16(acc[mf][2 * nfp + 0], a[mf], b[0], b[1]);
                        mma_f16(acc[mf][2 * nfp + 1], a[mf], b[2], b[3]);
                    }
                }
                if (NF & 1) {
                    int l = lane & 15;
                    int nrow = warpN * WN + (NF - 1) * 8 + (l & 7);
                    int u = 2 * ks + (l >> 3);
                    uint32_t b[2];
                    ldsm_x2(bBase + nrow * 128 + ((u ^ (nrow & 7)) << 4), b);
#pragma unroll
                    for (int mf = 0; mf < MF; mf++)
                        mma_f16(acc[mf][NF - 1], a[mf], b[0], b[1]);
                }
            }
        }
        __syncthreads();
    }

    // ---- epilogue ----
    if (EPI == 0) {
#pragma unroll
        for (int mf = 0; mf < MF; mf++) {
#pragma unroll
            for (int nf = 0; nf < NF; nf++) {
                int col = nbase + warpN * WN + nf * 8 + (lane & 3) * 2;
                float b0 = biasv[col], b1 = biasv[col + 1];
                int r0 = mrow0 + warpM * WM + mf * 16 + (lane >> 2);
                if (r0 < row_end) {
                    float2 v = make_float2(fmaxf(acc[mf][nf][0] + b0, 0.f),
                                           fmaxf(acc[mf][nf][1] + b1, 0.f));
                    *reinterpret_cast<float2*>(outp + (size_t)r0 * 128 + col) = v;
                }
                int r1 = r0 + 8;
                if (r1 < row_end) {
                    float2 v = make_float2(fmaxf(acc[mf][nf][2] + b0, 0.f),
                                           fmaxf(acc[mf][nf][3] + b1, 0.f));
                    *reinterpret_cast<float2*>(outp + (size_t)r1 * 128 + col) = v;
                }
            }
        }
    } else {
#pragma unroll
        for (int h = 0; h < 2; h++) {
            int row = mrow0 + wid * 16 + (lane >> 2) + h * 8;
            float v[2 * NF];
            float m = -INFINITY;
#pragma unroll
            for (int f = 0; f < NF; f++) {
                int col = f * 8 + (lane & 3) * 2;
                v[2 * f + 0] = acc[0][f][2 * h + 0] + biasv[col];
                v[2 * f + 1] = acc[0][f][2 * h + 1] + biasv[col + 1];
                m = fmaxf(m, fmaxf(v[2 * f], v[2 * f + 1]));
            }
            m = fmaxf(m, __shfl_xor_sync(0xFFFFFFFFu, m, 1));
            m = fmaxf(m, __shfl_xor_sync(0xFFFFFFFFu, m, 2));
            float s = 0.f;
#pragma unroll
            for (int j = 0; j < 2 * NF; j++) s += expf(v[j] - m);
            s += __shfl_xor_sync(0xFFFFFFFFu, s, 1);
            s += __shfl_xor_sync(0xFFFFFFFFu, s, 2);
            float l = m + logf(s);
            if (row < row_end) {
#pragma unroll
                for (int f = 0; f < NF; f++) {
                    int col = f * 8 + (lane & 3) * 2;
                    float2 o = make_float2(v[2 * f] - l, v[2 * f + 1] - l);
                    *reinterpret_cast<float2*>(outp + (size_t)row * 40 + col) = o;
                }
            }
        }
    }
}

// ---------------- launch ----------------
extern "C" void kernel_launch(void* const* d_in, const int* in_sizes, int n_in,
                              void* d_out, int out_size)
{
    const float* x0      = (const float*)d_in[0];
    const float* emb1    = (const float*)d_in[1];
    const float* rel_w1  = (const float*)d_in[2];
    const float* root_w1 = (const float*)d_in[3];
    const float* root_b1 = (const float*)d_in[4];
    const float* rel_w2  = (const float*)d_in[5];
    const float* root_w2 = (const float*)d_in[6];
    const float* root_b2 = (const float*)d_in[7];
    const int*   eidx    = (const int*)d_in[8];
    const int*   etype   = (const int*)d_in[9];
    (void)in_sizes; (void)n_in; (void)out_size;

    const int* src = eidx;
    const int* dst = eidx + N_EDGES;
    float* out = (float*)d_out;

    void *p_cnt, *p_h1r, *p_B1h, *p_B1l, *p_B2h, *p_B2l;
    cudaGetSymbolAddress(&p_cnt, g_cnt);
    cudaGetSymbolAddress(&p_h1r, g_h1r);
    cudaGetSymbolAddress(&p_B1h, g_B1h);
    cudaGetSymbolAddress(&p_B1l, g_B1l);
    cudaGetSymbolAddress(&p_B2h, g_B2h);
    cudaGetSymbolAddress(&p_B2l, g_B2l);

    constexpr int SMEM1 = 2 * (128 * KC * 2 + 2 * 64 * KC * 2);  // 65536
    constexpr int SMEM2 = 2 * (128 * KC * 2 + 2 * 40 * KC * 2);  // 53248
    cudaFuncSetAttribute(gemm_kernel<64, 0>, cudaFuncAttributeMaxDynamicSharedMemorySize, SMEM1);
    cudaFuncSetAttribute(gemm_kernel<40, 1>, cudaFuncAttributeMaxDynamicSharedMemorySize, SMEM2);

    // B weight split (tiny)
    prepB_kernel<128><<<(2 * 128 * K_TOT + 255) / 256, 256>>>(
        rel_w1, root_w1, (__half*)p_B1h, (__half*)p_B1l);
    prepB_kernel<40><<<(2 * 40 * K_TOT + 255) / 256, 256>>>(
        rel_w2, root_w2, (__half*)p_B2h, (__half*)p_B2l);

    // CSR build: count -> scan -> scatter
    cudaMemsetAsync(p_cnt, 0, sizeof(int) * SEG);
    count_kernel<<<(N_EDGES + 255) / 256, 256>>>(dst, etype);
    scanA_kernel<<<NBLK, 256>>>();
    scanB_kernel<<<1, 512>>>();
    scanC_kernel<<<NBLK, 256>>>();
    scatter_kernel<<<(N_EDGES + 255) / 256, 256>>>(src, dst, etype);

    const int AGG_BLOCKS = ((SEG + N_NODES) * 32 + 255) / 256;

    // layer 1: aggregation (+root fill, fp16) + pipelined GEMM -> g_h1r
    agg_kernel<0><<<AGG_BLOCKS, 256>>>(x0, emb1);
    gemm_kernel<64, 0><<<dim3(NTILES, 2), 256, SMEM1>>>(
        (const __half*)p_B1h, (const __half*)p_B1l, root_b1, (float*)p_h1r);

    // layer 2: aggregation (fp16) + GEMM -> d_out
    agg_kernel<1><<<AGG_BLOCKS, 256>>>((const float*)p_h1r, nullptr);
    gemm_kernel<40, 1><<<dim3(NTILES, 1), 256, SMEM2>>>(
        (const __half*)p_B2h, (const __half*)p_B2l, root_b2, out);
}

// round 15
// speedup vs baseline: 1.5086x; 1.0837x over previous
#include <cuda_runtime.h>
#include <cuda_fp16.h>
#include <cstdint>
#include <math.h>

// ---------------- problem constants ----------------
constexpr int N_NODES = 50000;
constexpr int N0      = 30000;
constexpr int N_EDGES = 600000;
constexpr int NT      = 8;
constexpr int K_TOT   = 1152;          // 8*128 rel + 128 root
constexpr int KC      = 64;
constexpr int NCHUNK  = K_TOT / KC;    // 18
constexpr int TILES0  = 235;           // ceil(30000/128)
constexpr int TILES1  = 157;           // ceil(20000/128)
constexpr int NTILES  = TILES0 + TILES1;
constexpr int N_PAD   = NTILES * 128;  // 50176 padded rows
constexpr int SEG     = NT * N_NODES;  // 400000 CSR segments, key = t*N + d
constexpr int NBLK    = (SEG + 1023) / 1024;  // 391

// ---------------- device scratch ----------------
__device__ __align__(16) __half g_h1r[(size_t)N_NODES * 128];  // relu(h1) fp16, 12.8 MB
__device__ int   g_cnt[SEG];
__device__ int   g_off[SEG + 1];
__device__ int   g_cur[SEG];
__device__ int   g_esrc[N_EDGES];
__device__ int   g_bsum[NBLK];
__device__ int   g_bpre[NBLK];
// A buffer: [N_PAD][1152] single fp16; padded rows never written -> stay zero.
__device__ __align__(16) __half g_agg[(size_t)N_PAD * K_TOT];  // 115.6 MB
__device__ __align__(16) __half g_B1[2 * 128 * K_TOT];
__device__ __align__(16) __half g_B2[2 * 40 * K_TOT];

// ---------------- helpers ----------------
__device__ __forceinline__ uint32_t smem_u32(const void* p) {
    uint32_t a;
    asm("{ .reg .u64 t; cvta.to.shared.u64 t, %1; cvt.u32.u64 %0, t; }" : "=r"(a) : "l"(p));
    return a;
}
__device__ __forceinline__ uint32_t pack_h2(float a, float b) {
    __half2 t = __floats2half2_rn(a, b);
    return *reinterpret_cast<uint32_t*>(&t);
}
__device__ __forceinline__ void cp16(uint32_t s, const void* g) {
    asm volatile("cp.async.cg.shared.global [%0], [%1], 16;" :: "r"(s), "l"(g));
}
__device__ __forceinline__ void cp_commit() {
    asm volatile("cp.async.commit_group;" ::: "memory");
}
template<int N>
__device__ __forceinline__ void cp_wait() {
    asm volatile("cp.async.wait_group %0;" :: "n"(N) : "memory");
}
__device__ __forceinline__ void ldsm_x4(uint32_t addr, uint32_t* r) {
    asm volatile("ldmatrix.sync.aligned.m8n8.x4.shared.b16 {%0,%1,%2,%3}, [%4];"
                 : "=r"(r[0]), "=r"(r[1]), "=r"(r[2]), "=r"(r[3]) : "r"(addr));
}
__device__ __forceinline__ void ldsm_x2(uint32_t addr, uint32_t* r) {
    asm volatile("ldmatrix.sync.aligned.m8n8.x2.shared.b16 {%0,%1}, [%2];"
                 : "=r"(r[0]), "=r"(r[1]) : "r"(addr));
}
__device__ __forceinline__ void mma_f16(float* c, const uint32_t* a, uint32_t b0, uint32_t b1) {
    asm volatile(
        "mma.sync.aligned.m16n8k16.row.col.f32.f16.f16.f32 "
        "{%0,%1,%2,%3}, {%4,%5,%6,%7}, {%8,%9}, {%0,%1,%2,%3};"
        : "+f"(c[0]), "+f"(c[1]), "+f"(c[2]), "+f"(c[3])
        : "r"(a[0]), "r"(a[1]), "r"(a[2]), "r"(a[3]), "r"(b0), "r"(b1));
}

// ---------------- CSR build ----------------
__global__ void count_kernel(const int* __restrict__ dst, const int* __restrict__ et) {
    int e = blockIdx.x * blockDim.x + threadIdx.x;
    if (e < N_EDGES) atomicAdd(&g_cnt[et[e] * N_NODES + dst[e]], 1);
}

__global__ void scanA_kernel() {
    __shared__ int sm[256];
    int base = blockIdx.x * 1024 + threadIdx.x * 4;
    int s = 0;
#pragma unroll
    for (int j = 0; j < 4; j++) { int i = base + j; if (i < SEG) s += g_cnt[i]; }
    sm[threadIdx.x] = s; __syncthreads();
    for (int off = 128; off > 0; off >>= 1) {
        if (threadIdx.x < off) sm[threadIdx.x] += sm[threadIdx.x + off];
        __syncthreads();
    }
    if (threadIdx.x == 0) g_bsum[blockIdx.x] = sm[0];
}

__global__ void scanB_kernel() {
    __shared__ int sm[512];
    int tid = threadIdx.x;
    int v = (tid < NBLK) ? g_bsum[tid] : 0;
    sm[tid] = v; __syncthreads();
    for (int off = 1; off < 512; off <<= 1) {
        int t = (tid >= off) ? sm[tid - off] : 0;
        __syncthreads();
        sm[tid] += t;
        __syncthreads();
    }
    if (tid < NBLK) g_bpre[tid] = sm[tid] - v;
    if (tid == 0) g_off[SEG] = N_EDGES;
}

__global__ void scanC_kernel() {
    __shared__ int sm[256];
    int tid = threadIdx.x;
    int base = blockIdx.x * 1024 + tid * 4;
    int c[4]; int ls = 0;
#pragma unroll
    for (int j = 0; j < 4; j++) { int i = base + j; c[j] = (i < SEG) ? g_cnt[i] : 0; ls += c[j]; }
    sm[tid] = ls; __syncthreads();
    for (int off = 1; off < 256; off <<= 1) {
        int t = (tid >= off) ? sm[tid - off] : 0;
        __syncthreads();
        sm[tid] += t;
        __syncthreads();
    }
    int run = g_bpre[blockIdx.x] + sm[tid] - ls;
#pragma unroll
    for (int j = 0; j < 4; j++) {
        int i = base + j;
        if (i < SEG) {
            g_off[i] = run; g_cur[i] = run;
            run += c[j];
        }
    }
}

__global__ void scatter_kernel(const int* __restrict__ src, const int* __restrict__ dst,
                               const int* __restrict__ et) {
    int e = blockIdx.x * blockDim.x + threadIdx.x;
    if (e >= N_EDGES) return;
    int key = et[e] * N_NODES + dst[e];
    int pos = atomicAdd(&g_cur[key], 1);
    g_esrc[pos] = src[e];
}

// ---------------- aggregation + root fill (atomic-free, warp per unit) ----------------
// units [0,SEG): agg[d][t*128+c] = mean of source rows (zeros if empty)
// units [SEG,SEG+N): agg[n][1024+c] = own features (root block)
// SRC 0: sources are fp32 x0/emb1. SRC 1: sources are fp16 g_h1r.
template<int SRC>
__global__ void agg_kernel(const float* __restrict__ R0, const float* __restrict__ R1)
{
    int w = (blockIdx.x * blockDim.x + threadIdx.x) >> 5;
    int lane = threadIdx.x & 31;
    if (w < SEG) {
        int t = w / N_NODES;
        int d = w - t * N_NODES;
        int o0 = g_off[w], o1 = g_off[w + 1];
        float4 acc = make_float4(0.f, 0.f, 0.f, 0.f);
        for (int e = o0; e < o1; e++) {
            int s = g_esrc[e];
            if (SRC == 0) {
                const float* xs = (s < N0) ? R0 + (size_t)s * 128
                                           : R1 + (size_t)(s - N0) * 128;
                float4 v = reinterpret_cast<const float4*>(xs)[lane];
                acc.x += v.x; acc.y += v.y; acc.z += v.z; acc.w += v.w;
            } else {
                uint2 hv = reinterpret_cast<const uint2*>(g_h1r + (size_t)s * 128)[lane];
                float2 p = __half22float2(*reinterpret_cast<__half2*>(&hv.x));
                float2 q = __half22float2(*reinterpret_cast<__half2*>(&hv.y));
                acc.x += p.x; acc.y += p.y; acc.z += q.x; acc.w += q.y;
            }
        }
        int len = o1 - o0;
        float inv = 1.0f / (float)(len < 1 ? 1 : len);
        uint2 hv;
        hv.x = pack_h2(acc.x * inv, acc.y * inv);
        hv.y = pack_h2(acc.z * inv, acc.w * inv);
        *reinterpret_cast<uint2*>(g_agg + (size_t)d * K_TOT + t * 128 + lane * 4) = hv;
    } else if (w < SEG + N_NODES) {
        int d = w - SEG;
        uint2 hv;
        if (SRC == 0) {
            const float* xs = (d < N0) ? R0 + (size_t)d * 128
                                       : R1 + (size_t)(d - N0) * 128;
            float4 v = reinterpret_cast<const float4*>(xs)[lane];
            hv.x = pack_h2(v.x, v.y);
            hv.y = pack_h2(v.z, v.w);
        } else {
            hv = reinterpret_cast<const uint2*>(g_h1r + (size_t)d * 128)[lane];
        }
        *reinterpret_cast<uint2*>(g_agg + (size_t)d * K_TOT + 1024 + lane * 4) = hv;
    }
}

// ---------------- B prep: single fp16 ----------------
template<int NB>
__global__ void prepB_kernel(const float* __restrict__ rel_w, const float* __restrict__ root_w,
                             __half* __restrict__ B)
{
    int i = blockIdx.x * blockDim.x + threadIdx.x;
    if (i >= 2 * NB * K_TOT) return;
    int k = i % K_TOT;
    int n = (i / K_TOT) % NB;
    int v = i / (K_TOT * NB);
    float w = (k < NT * 128) ? rel_w[(k >> 7) * NB * 128 + n * 128 + (k & 127)]
                             : root_w[v * NB * 128 + n * 128 + (k - NT * 128)];
    B[i] = __float2half_rn(w);
}

// ---------------- fp16 single-pass mma.sync GEMM, cp.async double buffered ----------------
// EPI 0: relu(D+bias) -> fp16 outp[row*128 + col], grid = dim3(NTILES, 2)
// EPI 1: log_softmax(D+bias) -> fp32 outp[row*40 + col], grid = dim3(NTILES, 1)
template<int BN, int EPI>
__global__ void __launch_bounds__(256, 2) gemm_kernel(
    const __half* __restrict__ B, const float* __restrict__ bias, void* __restrict__ outp_)
{
    constexpr int NBT = (EPI == 0) ? 128 : 40;
    constexpr int WARPS_M = (BN == 64) ? 4 : 8;
    constexpr int WARPS_N = (BN == 64) ? 2 : 1;
    constexpr int WM = 128 / WARPS_M;          // 32 or 16
    constexpr int WN = BN / WARPS_N;           // 32 or 40
    constexpr int MF = WM / 16;                // 2 or 1
    constexpr int NF = WN / 8;                 // 4 or 5
    constexpr int A_BYTES = 128 * KC * 2;      // 16384
    constexpr int B_BYTES = BN * KC * 2;
    constexpr int STAGE = A_BYTES + B_BYTES;

    extern __shared__ char smem[];
    const uint32_t sbase = smem_u32(smem);

    const int tid  = threadIdx.x;
    const int wid  = tid >> 5;
    const int lane = tid & 31;
    const int warpM = wid % WARPS_M;
    const int warpN = wid / WARPS_M;

    const int tile  = blockIdx.x;
    const int nbase = blockIdx.y * BN;
    const int var = (tile < TILES0) ? 0 : 1;
    const int mrow0 = var ? (N0 + (tile - TILES0) * 128) : (tile * 128);
    const int row_end = var ? N_NODES : N0;
    const __half* Bv = B + (size_t)var * NBT * K_TOT;
    const float* biasv = bias + var * NBT;
    const size_t aggRow0 = (size_t)mrow0 * K_TOT;

    float acc[MF][NF][4];
#pragma unroll
    for (int i = 0; i < MF; i++)
#pragma unroll
        for (int j = 0; j < NF; j++)
#pragma unroll
            for (int q = 0; q < 4; q++) acc[i][j][q] = 0.f;

    // ---- cp.async issue for chunk c into stage c&1 ----
    auto issue = [&](int c) {
        uint32_t ust = sbase + (c & 1) * STAGE;
        // A: 1024 x 16B
#pragma unroll
        for (int i = 0; i < 4; i++) {
            int idx = tid + i * 256;               // 0..1023
            int row = idx >> 3, u = idx & 7;
            const __half* gp = g_agg + aggRow0 + (size_t)row * K_TOT + c * KC + u * 8;
            cp16(ust + row * 128 + ((u ^ (row & 7)) << 4), gp);
        }
        // B: BN*8 x 16B
        constexpr int BITEMS = BN * 8;
#pragma unroll
        for (int j = 0; j < (BITEMS + 255) / 256; j++) {
            int idx = tid + j * 256;
            if ((BITEMS % 256 == 0) || idx < BITEMS) {
                int n = idx >> 3, u = idx & 7;
                const __half* gp = Bv + (size_t)(nbase + n) * K_TOT + c * KC + u * 8;
                cp16(ust + A_BYTES + n * 128 + ((u ^ (n & 7)) << 4), gp);
            }
        }
        cp_commit();
    };

    issue(0);
    for (int c = 0; c < NCHUNK; c++) {
        if (c + 1 < NCHUNK) { issue(c + 1); cp_wait<1>(); }
        else                { cp_wait<0>(); }
        __syncthreads();

        const uint32_t ust = sbase + (c & 1) * STAGE;
        const uint32_t uA  = ust;
        const uint32_t uB  = ust + A_BYTES;

#pragma unroll
        for (int ks = 0; ks < 4; ks++) {
            uint32_t a[MF][4];
#pragma unroll
            for (int mf = 0; mf < MF; mf++) {
                int row = warpM * WM + mf * 16 + (lane & 15);
                int u = 2 * ks + (lane >> 4);
                ldsm_x4(uA + row * 128 + ((u ^ (row & 7)) << 4), a[mf]);
            }
#pragma unroll
            for (int nfp = 0; nfp < NF / 2; nfp++) {
                int nrow = warpN * WN + nfp * 16 + ((lane >> 4) * 8) + (lane & 7);
                int u = 2 * ks + ((lane >> 3) & 1);
                uint32_t b[4];
                ldsm_x4(uB + nrow * 128 + ((u ^ (nrow & 7)) << 4), b);
#pragma unroll
                for (int mf = 0; mf < MF; mf++) {
                    mma_f16(acc[mf][2 * nfp + 0], a[mf], b[0], b[1]);
                    mma_f16(acc[mf][2 * nfp + 1], a[mf], b[2], b[3]);
                }
            }
            if (NF & 1) {
                int l = lane & 15;
                int nrow = warpN * WN + (NF - 1) * 8 + (l & 7);
                int u = 2 * ks + (l >> 3);
                uint32_t b[2];
                ldsm_x2(uB + nrow * 128 + ((u ^ (nrow & 7)) << 4), b);
#pragma unroll
                for (int mf = 0; mf < MF; mf++)
                    mma_f16(acc[mf][NF - 1], a[mf], b[0], b[1]);
            }
        }
        __syncthreads();
    }

    // ---- epilogue ----
    if (EPI == 0) {
        __half* outp = (__half*)outp_;
#pragma unroll
        for (int mf = 0; mf < MF; mf++) {
#pragma unroll
            for (int nf = 0; nf < NF; nf++) {
                int col = nbase + warpN * WN + nf * 8 + (lane & 3) * 2;
                float b0 = biasv[col], b1 = biasv[col + 1];
                int r0 = mrow0 + warpM * WM + mf * 16 + (lane >> 2);
                if (r0 < row_end) {
                    __half2 v = __floats2half2_rn(fmaxf(acc[mf][nf][0] + b0, 0.f),
                                                  fmaxf(acc[mf][nf][1] + b1, 0.f));
                    *reinterpret_cast<__half2*>(outp + (size_t)r0 * 128 + col) = v;
                }
                int r1 = r0 + 8;
                if (r1 < row_end) {
                    __half2 v = __floats2half2_rn(fmaxf(acc[mf][nf][2] + b0, 0.f),
                                                  fmaxf(acc[mf][nf][3] + b1, 0.f));
                    *reinterpret_cast<__half2*>(outp + (size_t)r1 * 128 + col) = v;
                }
            }
        }
    } else {
        float* outp = (float*)outp_;
#pragma unroll
        for (int h = 0; h < 2; h++) {
            int row = mrow0 + wid * 16 + (lane >> 2) + h * 8;
            float v[2 * NF];
            float m = -INFINITY;
#pragma unroll
            for (int f = 0; f < NF; f++) {
                int col = f * 8 + (lane & 3) * 2;
                v[2 * f + 0] = acc[0][f][2 * h + 0] + biasv[col];
                v[2 * f + 1] = acc[0][f][2 * h + 1] + biasv[col + 1];
                m = fmaxf(m, fmaxf(v[2 * f], v[2 * f + 1]));
            }
            m = fmaxf(m, __shfl_xor_sync(0xFFFFFFFFu, m, 1));
            m = fmaxf(m, __shfl_xor_sync(0xFFFFFFFFu, m, 2));
            float s = 0.f;
#pragma unroll
            for (int j = 0; j < 2 * NF; j++) s += expf(v[j] - m);
            s += __shfl_xor_sync(0xFFFFFFFFu, s, 1);
            s += __shfl_xor_sync(0xFFFFFFFFu, s, 2);
            float l = m + logf(s);
            if (row < row_end) {
#pragma unroll
                for (int f = 0; f < NF; f++) {
                    int col = f * 8 + (lane & 3) * 2;
                    float2 o = make_float2(v[2 * f] - l, v[2 * f + 1] - l);
                    *reinterpret_cast<float2*>(outp + (size_t)row * 40 + col) = o;
                }
            }
        }
    }
}

// ---------------- launch ----------------
extern "C" void kernel_launch(void* const* d_in, const int* in_sizes, int n_in,
                              void* d_out, int out_size)
{
    const float* x0      = (const float*)d_in[0];
    const float* emb1    = (const float*)d_in[1];
    const float* rel_w1  = (const float*)d_in[2];
    const float* root_w1 = (const float*)d_in[3];
    const float* root_b1 = (const float*)d_in[4];
    const float* rel_w2  = (const float*)d_in[5];
    const float* root_w2 = (const float*)d_in[6];
    const float* root_b2 = (const float*)d_in[7];
    const int*   eidx    = (const int*)d_in[8];
    const int*   etype   = (const int*)d_in[9];
    (void)in_sizes; (void)n_in; (void)out_size;

    const int* src = eidx;
    const int* dst = eidx + N_EDGES;
    float* out = (float*)d_out;

    void *p_cnt, *p_h1r, *p_B1, *p_B2;
    cudaGetSymbolAddress(&p_cnt, g_cnt);
    cudaGetSymbolAddress(&p_h1r, g_h1r);
    cudaGetSymbolAddress(&p_B1, g_B1);
    cudaGetSymbolAddress(&p_B2, g_B2);

    constexpr int SMEM1 = 2 * (128 * KC * 2 + 64 * KC * 2);  // 49152
    constexpr int SMEM2 = 2 * (128 * KC * 2 + 40 * KC * 2);  // 43008
    cudaFuncSetAttribute(gemm_kernel<64, 0>, cudaFuncAttributeMaxDynamicSharedMemorySize, SMEM1);
    cudaFuncSetAttribute(gemm_kernel<40, 1>, cudaFuncAttributeMaxDynamicSharedMemorySize, SMEM2);

    // B weight conversion (tiny)
    prepB_kernel<128><<<(2 * 128 * K_TOT + 255) / 256, 256>>>(rel_w1, root_w1, (__half*)p_B1);
    prepB_kernel<40><<<(2 * 40 * K_TOT + 255) / 256, 256>>>(rel_w2, root_w2, (__half*)p_B2);

    // CSR build: count -> scan -> scatter
    cudaMemsetAsync(p_cnt, 0, sizeof(int) * SEG);
    count_kernel<<<(N_EDGES + 255) / 256, 256>>>(dst, etype);
    scanA_kernel<<<NBLK, 256>>>();
    scanB_kernel<<<1, 512>>>();
    scanC_kernel<<<NBLK, 256>>>();
    scatter_kernel<<<(N_EDGES + 255) / 256, 256>>>(src, dst, etype);

    const int AGG_BLOCKS = ((SEG + N_NODES) * 32 + 255) / 256;

    // layer 1: aggregation (+root fill, fp16) + pipelined GEMM -> g_h1r (fp16)
    agg_kernel<0><<<AGG_BLOCKS, 256>>>(x0, emb1);
    gemm_kernel<64, 0><<<dim3(NTILES, 2), 256, SMEM1>>>(
        (const __half*)p_B1, root_b1, p_h1r);

    // layer 2: aggregation (fp16 sources) + GEMM -> d_out
    agg_kernel<1><<<AGG_BLOCKS, 256>>>(nullptr, nullptr);
    gemm_kernel<40, 1><<<dim3(NTILES, 1), 256, SMEM2>>>(
        (const __half*)p_B2, root_b2, out);
}

// round 16
// speedup vs baseline: 1.6142x; 1.0700x over previous
#include <cuda_runtime.h>
#include <cuda_fp16.h>
#include <cstdint>
#include <math.h>

// ---------------- problem constants ----------------
constexpr int N_NODES = 50000;
constexpr int N0      = 30000;
constexpr int N_EDGES = 600000;
constexpr int NT      = 8;
constexpr int K_TOT   = 1152;          // 8*128 rel + 128 root
constexpr int KC      = 64;
constexpr int NCHUNK  = K_TOT / KC;    // 18
constexpr int TILES0  = 235;           // ceil(30000/128)
constexpr int TILES1  = 157;           // ceil(20000/128)
constexpr int NTILES  = TILES0 + TILES1;
constexpr int N_PAD   = NTILES * 128;  // 50176 padded rows
constexpr int SEG     = NT * N_NODES;  // 400000 CSR segments, key = t*N + d
constexpr int NBLK    = (SEG + 1023) / 1024;  // 391

// ---------------- device scratch ----------------
__device__ __align__(16) __half g_h1r[(size_t)N_NODES * 128];  // relu(h1) fp16, 12.8 MB
__device__ int   g_cnt[SEG];
__device__ int   g_off[SEG + 1];
__device__ int   g_cur[SEG];
__device__ int   g_esrc[N_EDGES];
__device__ int   g_bsum[NBLK];
__device__ int   g_bpre[NBLK];
// A buffer: [N_PAD][1152] single fp16; padded rows never written -> stay zero.
__device__ __align__(16) __half g_agg[(size_t)N_PAD * K_TOT];  // 115.6 MB
__device__ __align__(16) __half g_B1[2 * 128 * K_TOT];
__device__ __align__(16) __half g_B2[2 * 40 * K_TOT];

// ---------------- helpers ----------------
__device__ __forceinline__ uint32_t smem_u32(const void* p) {
    uint32_t a;
    asm("{ .reg .u64 t; cvta.to.shared.u64 t, %1; cvt.u32.u64 %0, t; }" : "=r"(a) : "l"(p));
    return a;
}
__device__ __forceinline__ uint32_t pack_h2(float a, float b) {
    __half2 t = __floats2half2_rn(a, b);
    return *reinterpret_cast<uint32_t*>(&t);
}
__device__ __forceinline__ void cp16(uint32_t s, const void* g) {
    asm volatile("cp.async.cg.shared.global [%0], [%1], 16;" :: "r"(s), "l"(g));
}
__device__ __forceinline__ void cp_commit() {
    asm volatile("cp.async.commit_group;" ::: "memory");
}
template<int N>
__device__ __forceinline__ void cp_wait() {
    asm volatile("cp.async.wait_group %0;" :: "n"(N) : "memory");
}
__device__ __forceinline__ void ldsm_x4(uint32_t addr, uint32_t* r) {
    asm volatile("ldmatrix.sync.aligned.m8n8.x4.shared.b16 {%0,%1,%2,%3}, [%4];"
                 : "=r"(r[0]), "=r"(r[1]), "=r"(r[2]), "=r"(r[3]) : "r"(addr));
}
__device__ __forceinline__ void ldsm_x2(uint32_t addr, uint32_t* r) {
    asm volatile("ldmatrix.sync.aligned.m8n8.x2.shared.b16 {%0,%1}, [%2];"
                 : "=r"(r[0]), "=r"(r[1]) : "r"(addr));
}
__device__ __forceinline__ void mma_f16(float* c, const uint32_t* a, uint32_t b0, uint32_t b1) {
    asm volatile(
        "mma.sync.aligned.m16n8k16.row.col.f32.f16.f16.f32 "
        "{%0,%1,%2,%3}, {%4,%5,%6,%7}, {%8,%9}, {%0,%1,%2,%3};"
        : "+f"(c[0]), "+f"(c[1]), "+f"(c[2]), "+f"(c[3])
        : "r"(a[0]), "r"(a[1]), "r"(a[2]), "r"(a[3]), "r"(b0), "r"(b1));
}

// ---------------- CSR build ----------------
__global__ void count_kernel(const int* __restrict__ dst, const int* __restrict__ et) {
    int e = blockIdx.x * blockDim.x + threadIdx.x;
    if (e < N_EDGES) atomicAdd(&g_cnt[et[e] * N_NODES + dst[e]], 1);
}

__global__ void scanA_kernel() {
    __shared__ int sm[256];
    int base = blockIdx.x * 1024 + threadIdx.x * 4;
    int s = 0;
#pragma unroll
    for (int j = 0; j < 4; j++) { int i = base + j; if (i < SEG) s += g_cnt[i]; }
    sm[threadIdx.x] = s; __syncthreads();
    for (int off = 128; off > 0; off >>= 1) {
        if (threadIdx.x < off) sm[threadIdx.x] += sm[threadIdx.x + off];
        __syncthreads();
    }
    if (threadIdx.x == 0) g_bsum[blockIdx.x] = sm[0];
}

__global__ void scanB_kernel() {
    __shared__ int sm[512];
    int tid = threadIdx.x;
    int v = (tid < NBLK) ? g_bsum[tid] : 0;
    sm[tid] = v; __syncthreads();
    for (int off = 1; off < 512; off <<= 1) {
        int t = (tid >= off) ? sm[tid - off] : 0;
        __syncthreads();
        sm[tid] += t;
        __syncthreads();
    }
    if (tid < NBLK) g_bpre[tid] = sm[tid] - v;
    if (tid == 0) g_off[SEG] = N_EDGES;
}

__global__ void scanC_kernel() {
    __shared__ int sm[256];
    int tid = threadIdx.x;
    int base = blockIdx.x * 1024 + tid * 4;
    int c[4]; int ls = 0;
#pragma unroll
    for (int j = 0; j < 4; j++) { int i = base + j; c[j] = (i < SEG) ? g_cnt[i] : 0; ls += c[j]; }
    sm[tid] = ls; __syncthreads();
    for (int off = 1; off < 256; off <<= 1) {
        int t = (tid >= off) ? sm[tid - off] : 0;
        __syncthreads();
        sm[tid] += t;
        __syncthreads();
    }
    int run = g_bpre[blockIdx.x] + sm[tid] - ls;
#pragma unroll
    for (int j = 0; j < 4; j++) {
        int i = base + j;
        if (i < SEG) {
            g_off[i] = run; g_cur[i] = run;
            run += c[j];
        }
    }
}

__global__ void scatter_kernel(const int* __restrict__ src, const int* __restrict__ dst,
                               const int* __restrict__ et) {
    int e = blockIdx.x * blockDim.x + threadIdx.x;
    if (e >= N_EDGES) return;
    int key = et[e] * N_NODES + dst[e];
    int pos = atomicAdd(&g_cur[key], 1);
    g_esrc[pos] = src[e];
}

// ---------------- aggregation + root fill (atomic-free, warp per unit) ----------------
// units [0,SEG): agg[d][t*128+c] = mean of source rows (zeros if empty)
// units [SEG,SEG+N): agg[n][1024+c] = own features (root block)
// SRC 0: sources are fp32 x0/emb1. SRC 1: sources are fp16 g_h1r.
template<int SRC>
__global__ void agg_kernel(const float* __restrict__ R0, const float* __restrict__ R1)
{
    int w = (blockIdx.x * blockDim.x + threadIdx.x) >> 5;
    int lane = threadIdx.x & 31;
    if (w < SEG) {
        int t = w / N_NODES;
        int d = w - t * N_NODES;
        int o0 = g_off[w], o1 = g_off[w + 1];
        float4 acc = make_float4(0.f, 0.f, 0.f, 0.f);
        for (int e = o0; e < o1; e++) {
            int s = g_esrc[e];
            if (SRC == 0) {
                const float* xs = (s < N0) ? R0 + (size_t)s * 128
                                           : R1 + (size_t)(s - N0) * 128;
                float4 v = reinterpret_cast<const float4*>(xs)[lane];
                acc.x += v.x; acc.y += v.y; acc.z += v.z; acc.w += v.w;
            } else {
                uint2 hv = reinterpret_cast<const uint2*>(g_h1r + (size_t)s * 128)[lane];
                float2 p = __half22float2(*reinterpret_cast<__half2*>(&hv.x));
                float2 q = __half22float2(*reinterpret_cast<__half2*>(&hv.y));
                acc.x += p.x; acc.y += p.y; acc.z += q.x; acc.w += q.y;
            }
        }
        int len = o1 - o0;
        float inv = 1.0f / (float)(len < 1 ? 1 : len);
        uint2 hv;
        hv.x = pack_h2(acc.x * inv, acc.y * inv);
        hv.y = pack_h2(acc.z * inv, acc.w * inv);
        *reinterpret_cast<uint2*>(g_agg + (size_t)d * K_TOT + t * 128 + lane * 4) = hv;
    } else if (w < SEG + N_NODES) {
        int d = w - SEG;
        uint2 hv;
        if (SRC == 0) {
            const float* xs = (d < N0) ? R0 + (size_t)d * 128
                                       : R1 + (size_t)(d - N0) * 128;
            float4 v = reinterpret_cast<const float4*>(xs)[lane];
            hv.x = pack_h2(v.x, v.y);
            hv.y = pack_h2(v.z, v.w);
        } else {
            hv = reinterpret_cast<const uint2*>(g_h1r + (size_t)d * 128)[lane];
        }
        *reinterpret_cast<uint2*>(g_agg + (size_t)d * K_TOT + 1024 + lane * 4) = hv;
    }
}

// ---------------- B prep: single fp16 ----------------
template<int NB>
__global__ void prepB_kernel(const float* __restrict__ rel_w, const float* __restrict__ root_w,
                             __half* __restrict__ B)
{
    int i = blockIdx.x * blockDim.x + threadIdx.x;
    if (i >= 2 * NB * K_TOT) return;
    int k = i % K_TOT;
    int n = (i / K_TOT) % NB;
    int v = i / (K_TOT * NB);
    float w = (k < NT * 128) ? rel_w[(k >> 7) * NB * 128 + n * 128 + (k & 127)]
                             : root_w[v * NB * 128 + n * 128 + (k - NT * 128)];
    B[i] = __float2half_rn(w);
}

// ---------------- fp16 single-pass mma.sync GEMM, cp.async double buffered ----------------
// EPI 0: BN=128, ONE CTA per M-tile (A read once), relu(D+bias) -> fp16 out, grid (NTILES)
// EPI 1: BN=40, log_softmax(D+bias) -> fp32 out, grid (NTILES)
template<int BN, int EPI>
__global__ void __launch_bounds__(256, 2) gemm_kernel(
    const __half* __restrict__ B, const float* __restrict__ bias, void* __restrict__ outp_)
{
    constexpr int NBT = (EPI == 0) ? 128 : 40;
    constexpr int WARPS_M = (BN == 128) ? 4 : 8;
    constexpr int WARPS_N = (BN == 128) ? 2 : 1;
    constexpr int WM = 128 / WARPS_M;          // 32 or 16
    constexpr int WN = BN / WARPS_N;           // 64 or 40
    constexpr int MF = WM / 16;                // 2 or 1
    constexpr int NF = WN / 8;                 // 8 or 5
    constexpr int A_BYTES = 128 * KC * 2;      // 16384
    constexpr int B_BYTES = BN * KC * 2;
    constexpr int STAGE = A_BYTES + B_BYTES;

    extern __shared__ char smem[];
    const uint32_t sbase = smem_u32(smem);

    const int tid  = threadIdx.x;
    const int wid  = tid >> 5;
    const int lane = tid & 31;
    const int warpM = wid % WARPS_M;
    const int warpN = wid / WARPS_M;

    const int tile = blockIdx.x;
    const int var = (tile < TILES0) ? 0 : 1;
    const int mrow0 = var ? (N0 + (tile - TILES0) * 128) : (tile * 128);
    const int row_end = var ? N_NODES : N0;
    const __half* Bv = B + (size_t)var * NBT * K_TOT;
    const float* biasv = bias + var * NBT;
    const size_t aggRow0 = (size_t)mrow0 * K_TOT;

    float acc[MF][NF][4];
#pragma unroll
    for (int i = 0; i < MF; i++)
#pragma unroll
        for (int j = 0; j < NF; j++)
#pragma unroll
            for (int q = 0; q < 4; q++) acc[i][j][q] = 0.f;

    // ---- cp.async issue for chunk c into stage c&1 ----
    auto issue = [&](int c) {
        uint32_t ust = sbase + (c & 1) * STAGE;
        // A: 1024 x 16B
#pragma unroll
        for (int i = 0; i < 4; i++) {
            int idx = tid + i * 256;               // 0..1023
            int row = idx >> 3, u = idx & 7;
            const __half* gp = g_agg + aggRow0 + (size_t)row * K_TOT + c * KC + u * 8;
            cp16(ust + row * 128 + ((u ^ (row & 7)) << 4), gp);
        }
        // B: BN*8 x 16B
        constexpr int BITEMS = BN * 8;
#pragma unroll
        for (int j = 0; j < (BITEMS + 255) / 256; j++) {
            int idx = tid + j * 256;
            if ((BITEMS % 256 == 0) || idx < BITEMS) {
                int n = idx >> 3, u = idx & 7;
                const __half* gp = Bv + (size_t)n * K_TOT + c * KC + u * 8;
                cp16(ust + A_BYTES + n * 128 + ((u ^ (n & 7)) << 4), gp);
            }
        }
        cp_commit();
    };

    issue(0);
    for (int c = 0; c < NCHUNK; c++) {
        if (c + 1 < NCHUNK) { issue(c + 1); cp_wait<1>(); }
        else                { cp_wait<0>(); }
        __syncthreads();

        const uint32_t ust = sbase + (c & 1) * STAGE;
        const uint32_t uA  = ust;
        const uint32_t uB  = ust + A_BYTES;

#pragma unroll
        for (int ks = 0; ks < 4; ks++) {
            uint32_t a[MF][4];
#pragma unroll
            for (int mf = 0; mf < MF; mf++) {
                int row = warpM * WM + mf * 16 + (lane & 15);
                int u = 2 * ks + (lane >> 4);
                ldsm_x4(uA + row * 128 + ((u ^ (row & 7)) << 4), a[mf]);
            }
#pragma unroll
            for (int nfp = 0; nfp < NF / 2; nfp++) {
                int nrow = warpN * WN + nfp * 16 + ((lane >> 4) * 8) + (lane & 7);
                int u = 2 * ks + ((lane >> 3) & 1);
                uint32_t b[4];
                ldsm_x4(uB + nrow * 128 + ((u ^ (nrow & 7)) << 4), b);
#pragma unroll
                for (int mf = 0; mf < MF; mf++) {
                    mma_f16(acc[mf][2 * nfp + 0], a[mf], b[0], b[1]);
                    mma_f16(acc[mf][2 * nfp + 1], a[mf], b[2], b[3]);
                }
            }
            if (NF & 1) {
                int l = lane & 15;
                int nrow = warpN * WN + (NF - 1) * 8 + (l & 7);
                int u = 2 * ks + (l >> 3);
                uint32_t b[2];
                ldsm_x2(uB + nrow * 128 + ((u ^ (nrow & 7)) << 4), b);
#pragma unroll
                for (int mf = 0; mf < MF; mf++)
                    mma_f16(acc[mf][NF - 1], a[mf], b[0], b[1]);
            }
        }
        __syncthreads();
    }

    // ---- epilogue ----
    if (EPI == 0) {
        __half* outp = (__half*)outp_;
#pragma unroll
        for (int mf = 0; mf < MF; mf++) {
#pragma unroll
            for (int nf = 0; nf < NF; nf++) {
                int col = warpN * WN + nf * 8 + (lane & 3) * 2;
                float b0 = biasv[col], b1 = biasv[col + 1];
                int r0 = mrow0 + warpM * WM + mf * 16 + (lane >> 2);
                if (r0 < row_end) {
                    __half2 v = __floats2half2_rn(fmaxf(acc[mf][nf][0] + b0, 0.f),
                                                  fmaxf(acc[mf][nf][1] + b1, 0.f));
                    *reinterpret_cast<__half2*>(outp + (size_t)r0 * 128 + col) = v;
                }
                int r1 = r0 + 8;
                if (r1 < row_end) {
                    __half2 v = __floats2half2_rn(fmaxf(acc[mf][nf][2] + b0, 0.f),
                                                  fmaxf(acc[mf][nf][3] + b1, 0.f));
                    *reinterpret_cast<__half2*>(outp + (size_t)r1 * 128 + col) = v;
                }
            }
        }
    } else {
        float* outp = (float*)outp_;
#pragma unroll
        for (int h = 0; h < 2; h++) {
            int row = mrow0 + wid * 16 + (lane >> 2) + h * 8;
            float v[2 * NF];
            float m = -INFINITY;
#pragma unroll
            for (int f = 0; f < NF; f++) {
                int col = f * 8 + (lane & 3) * 2;
                v[2 * f + 0] = acc[0][f][2 * h + 0] + biasv[col];
                v[2 * f + 1] = acc[0][f][2 * h + 1] + biasv[col + 1];
                m = fmaxf(m, fmaxf(v[2 * f], v[2 * f + 1]));
            }
            m = fmaxf(m, __shfl_xor_sync(0xFFFFFFFFu, m, 1));
            m = fmaxf(m, __shfl_xor_sync(0xFFFFFFFFu, m, 2));
            float s = 0.f;
#pragma unroll
            for (int j = 0; j < 2 * NF; j++) s += expf(v[j] - m);
            s += __shfl_xor_sync(0xFFFFFFFFu, s, 1);
            s += __shfl_xor_sync(0xFFFFFFFFu, s, 2);
            float l = m + logf(s);
            if (row < row_end) {
#pragma unroll
                for (int f = 0; f < NF; f++) {
                    int col = f * 8 + (lane & 3) * 2;
                    float2 o = make_float2(v[2 * f] - l, v[2 * f + 1] - l);
                    *reinterpret_cast<float2*>(outp + (size_t)row * 40 + col) = o;
                }
            }
        }
    }
}

// ---------------- launch ----------------
extern "C" void kernel_launch(void* const* d_in, const int* in_sizes, int n_in,
                              void* d_out, int out_size)
{
    const float* x0      = (const float*)d_in[0];
    const float* emb1    = (const float*)d_in[1];
    const float* rel_w1  = (const float*)d_in[2];
    const float* root_w1 = (const float*)d_in[3];
    const float* root_b1 = (const float*)d_in[4];
    const float* rel_w2  = (const float*)d_in[5];
    const float* root_w2 = (const float*)d_in[6];
    const float* root_b2 = (const float*)d_in[7];
    const int*   eidx    = (const int*)d_in[8];
    const int*   etype   = (const int*)d_in[9];
    (void)in_sizes; (void)n_in; (void)out_size;

    const int* src = eidx;
    const int* dst = eidx + N_EDGES;
    float* out = (float*)d_out;

    void *p_cnt, *p_h1r, *p_B1, *p_B2;
    cudaGetSymbolAddress(&p_cnt, g_cnt);
    cudaGetSymbolAddress(&p_h1r, g_h1r);
    cudaGetSymbolAddress(&p_B1, g_B1);
    cudaGetSymbolAddress(&p_B2, g_B2);

    constexpr int SMEM1 = 2 * (128 * KC * 2 + 128 * KC * 2);  // 65536
    constexpr int SMEM2 = 2 * (128 * KC * 2 + 40 * KC * 2);   // 43008
    cudaFuncSetAttribute(gemm_kernel<128, 0>, cudaFuncAttributeMaxDynamicSharedMemorySize, SMEM1);
    cudaFuncSetAttribute(gemm_kernel<40, 1>,  cudaFuncAttributeMaxDynamicSharedMemorySize, SMEM2);

    // B weight conversion (tiny)
    prepB_kernel<128><<<(2 * 128 * K_TOT + 255) / 256, 256>>>(rel_w1, root_w1, (__half*)p_B1);
    prepB_kernel<40><<<(2 * 40 * K_TOT + 255) / 256, 256>>>(rel_w2, root_w2, (__half*)p_B2);

    // CSR build: count -> scan -> scatter
    cudaMemsetAsync(p_cnt, 0, sizeof(int) * SEG);
    count_kernel<<<(N_EDGES + 255) / 256, 256>>>(dst, etype);
    scanA_kernel<<<NBLK, 256>>>();
    scanB_kernel<<<1, 512>>>();
    scanC_kernel<<<NBLK, 256>>>();
    scatter_kernel<<<(N_EDGES + 255) / 256, 256>>>(src, dst, etype);

    const int AGG_BLOCKS = ((SEG + N_NODES) * 32 + 255) / 256;

    // layer 1: aggregation (+root fill, fp16) + single-A-pass GEMM -> g_h1r (fp16)
    agg_kernel<0><<<AGG_BLOCKS, 256>>>(x0, emb1);
    gemm_kernel<128, 0><<<NTILES, 256, SMEM1>>>((const __half*)p_B1, root_b1, p_h1r);

    // layer 2: aggregation (fp16 sources) + GEMM -> d_out
    agg_kernel<1><<<AGG_BLOCKS, 256>>>(nullptr, nullptr);
    gemm_kernel<40, 1><<<NTILES, 256, SMEM2>>>((const __half*)p_B2, root_b2, out);
}

// round 17
// speedup vs baseline: 1.6453x; 1.0192x over previous
#include <cuda_runtime.h>
#include <cuda_fp16.h>
#include <cstdint>
#include <math.h>

// ---------------- problem constants ----------------
constexpr int N_NODES = 50000;
constexpr int N0      = 30000;
constexpr int N_EDGES = 600000;
constexpr int NT      = 8;
constexpr int K_TOT   = 1152;          // 8*128 rel + 128 root
constexpr int KC      = 64;
constexpr int NCHUNK  = K_TOT / KC;    // 18
constexpr int TILES0  = 235;           // ceil(30000/128)
constexpr int TILES1  = 157;           // ceil(20000/128)
constexpr int NTILES  = TILES0 + TILES1;
constexpr int N_PAD   = NTILES * 128;  // 50176 padded rows
constexpr int SEG     = NT * N_NODES;  // 400000 CSR segments, key = t*N + d
constexpr int NBLK    = (SEG + 1023) / 1024;  // 391

// ---------------- device scratch ----------------
__device__ __align__(16) __half g_h1r[(size_t)N_NODES * 128];  // relu(h1) fp16, 12.8 MB
__device__ __align__(16) __half g_xh [(size_t)N_NODES * 128];  // fp16 input features, 12.8 MB
__device__ int   g_cnt[SEG];
__device__ int   g_off[SEG + 1];
__device__ int   g_cur[SEG];
__device__ int   g_esrc[N_EDGES];
__device__ int   g_bsum[NBLK];
__device__ int   g_bpre[NBLK];
// A buffer: [N_PAD][1152] single fp16. Zero-init at module load; empty-segment
// entries and padded rows are never written and stay zero (deterministic).
__device__ __align__(16) __half g_agg[(size_t)N_PAD * K_TOT];  // 115.6 MB
__device__ __align__(16) __half g_B1[2 * 128 * K_TOT];
__device__ __align__(16) __half g_B2[2 * 40 * K_TOT];

// ---------------- helpers ----------------
__device__ __forceinline__ uint32_t smem_u32(const void* p) {
    uint32_t a;
    asm("{ .reg .u64 t; cvta.to.shared.u64 t, %1; cvt.u32.u64 %0, t; }" : "=r"(a) : "l"(p));
    return a;
}
__device__ __forceinline__ uint32_t pack_h2(float a, float b) {
    __half2 t = __floats2half2_rn(a, b);
    return *reinterpret_cast<uint32_t*>(&t);
}
__device__ __forceinline__ void cp16(uint32_t s, const void* g) {
    asm volatile("cp.async.cg.shared.global [%0], [%1], 16;" :: "r"(s), "l"(g));
}
__device__ __forceinline__ void cp_commit() {
    asm volatile("cp.async.commit_group;" ::: "memory");
}
template<int N>
__device__ __forceinline__ void cp_wait() {
    asm volatile("cp.async.wait_group %0;" :: "n"(N) : "memory");
}
__device__ __forceinline__ void ldsm_x4(uint32_t addr, uint32_t* r) {
    asm volatile("ldmatrix.sync.aligned.m8n8.x4.shared.b16 {%0,%1,%2,%3}, [%4];"
                 : "=r"(r[0]), "=r"(r[1]), "=r"(r[2]), "=r"(r[3]) : "r"(addr));
}
__device__ __forceinline__ void ldsm_x2(uint32_t addr, uint32_t* r) {
    asm volatile("ldmatrix.sync.aligned.m8n8.x2.shared.b16 {%0,%1}, [%2];"
                 : "=r"(r[0]), "=r"(r[1]) : "r"(addr));
}
__device__ __forceinline__ void mma_f16(float* c, const uint32_t* a, uint32_t b0, uint32_t b1) {
    asm volatile(
        "mma.sync.aligned.m16n8k16.row.col.f32.f16.f16.f32 "
        "{%0,%1,%2,%3}, {%4,%5,%6,%7}, {%8,%9}, {%0,%1,%2,%3};"
        : "+f"(c[0]), "+f"(c[1]), "+f"(c[2]), "+f"(c[3])
        : "r"(a[0]), "r"(a[1]), "r"(a[2]), "r"(a[3]), "r"(b0), "r"(b1));
}

// ---------------- input fp16 conversion ----------------
__global__ void convx_kernel(const float* __restrict__ x0, const float* __restrict__ emb1) {
    int i = blockIdx.x * blockDim.x + threadIdx.x;      // one float4 -> half4
    if (i >= N_NODES * 32) return;
    int node = i >> 5, q = i & 31;
    const float* xs = (node < N0) ? x0 + (size_t)node * 128
                                  : emb1 + (size_t)(node - N0) * 128;
    float4 v = reinterpret_cast<const float4*>(xs)[q];
    uint2 hv;
    hv.x = pack_h2(v.x, v.y);
    hv.y = pack_h2(v.z, v.w);
    *reinterpret_cast<uint2*>(g_xh + (size_t)node * 128 + q * 4) = hv;
}

// ---------------- CSR build ----------------
__global__ void count_kernel(const int* __restrict__ dst, const int* __restrict__ et) {
    int e = blockIdx.x * blockDim.x + threadIdx.x;
    if (e < N_EDGES) atomicAdd(&g_cnt[et[e] * N_NODES + dst[e]], 1);
}

__global__ void scanA_kernel() {
    __shared__ int sm[256];
    int base = blockIdx.x * 1024 + threadIdx.x * 4;
    int s = 0;
#pragma unroll
    for (int j = 0; j < 4; j++) { int i = base + j; if (i < SEG) s += g_cnt[i]; }
    sm[threadIdx.x] = s; __syncthreads();
    for (int off = 128; off > 0; off >>= 1) {
        if (threadIdx.x < off) sm[threadIdx.x] += sm[threadIdx.x + off];
        __syncthreads();
    }
    if (threadIdx.x == 0) g_bsum[blockIdx.x] = sm[0];
}

__global__ void scanB_kernel() {
    __shared__ int sm[512];
    int tid = threadIdx.x;
    int v = (tid < NBLK) ? g_bsum[tid] : 0;
    sm[tid] = v; __syncthreads();
    for (int off = 1; off < 512; off <<= 1) {
        int t = (tid >= off) ? sm[tid - off] : 0;
        __syncthreads();
        sm[tid] += t;
        __syncthreads();
    }
    if (tid < NBLK) g_bpre[tid] = sm[tid] - v;
    if (tid == 0) g_off[SEG] = N_EDGES;
}

__global__ void scanC_kernel() {
    __shared__ int sm[256];
    int tid = threadIdx.x;
    int base = blockIdx.x * 1024 + tid * 4;
    int c[4]; int ls = 0;
#pragma unroll
    for (int j = 0; j < 4; j++) { int i = base + j; c[j] = (i < SEG) ? g_cnt[i] : 0; ls += c[j]; }
    sm[tid] = ls; __syncthreads();
    for (int off = 1; off < 256; off <<= 1) {
        int t = (tid >= off) ? sm[tid - off] : 0;
        __syncthreads();
        sm[tid] += t;
        __syncthreads();
    }
    int run = g_bpre[blockIdx.x] + sm[tid] - ls;
#pragma unroll
    for (int j = 0; j < 4; j++) {
        int i = base + j;
        if (i < SEG) {
            g_off[i] = run; g_cur[i] = run;
            run += c[j];
        }
    }
}

__global__ void scatter_kernel(const int* __restrict__ src, const int* __restrict__ dst,
                               const int* __restrict__ et) {
    int e = blockIdx.x * blockDim.x + threadIdx.x;
    if (e >= N_EDGES) return;
    int key = et[e] * N_NODES + dst[e];
    int pos = atomicAdd(&g_cur[key], 1);
    g_esrc[pos] = src[e];
}

// ---------------- aggregation + root fill (atomic-free, warp per unit) ----------------
// units [0,SEG): agg[d][t*128+c] = mean of source rows; EMPTY segments skipped
//                (entries never written, stay zero from module-load init).
// units [SEG,SEG+N): agg[n][1024+c] = own features (root block, always written)
// Sources: SRC 0 -> g_xh (fp16 inputs), SRC 1 -> g_h1r (fp16 layer-1 output).
template<int SRC>
__global__ void agg_kernel()
{
    int w = (blockIdx.x * blockDim.x + threadIdx.x) >> 5;
    int lane = threadIdx.x & 31;
    const __half* XS = (SRC == 0) ? g_xh : g_h1r;
    if (w < SEG) {
        int o0 = g_off[w], o1 = g_off[w + 1];
        int len = o1 - o0;
        if (len == 0) return;                     // zeros persist (zero-init)
        int t = w / N_NODES;
        int d = w - t * N_NODES;
        float4 acc = make_float4(0.f, 0.f, 0.f, 0.f);
        for (int e = o0; e < o1; e++) {
            int s = g_esrc[e];
            uint2 hv = reinterpret_cast<const uint2*>(XS + (size_t)s * 128)[lane];
            float2 p = __half22float2(*reinterpret_cast<__half2*>(&hv.x));
            float2 q = __half22float2(*reinterpret_cast<__half2*>(&hv.y));
            acc.x += p.x; acc.y += p.y; acc.z += q.x; acc.w += q.y;
        }
        float inv = 1.0f / (float)len;
        uint2 hv;
        hv.x = pack_h2(acc.x * inv, acc.y * inv);
        hv.y = pack_h2(acc.z * inv, acc.w * inv);
        *reinterpret_cast<uint2*>(g_agg + (size_t)d * K_TOT + t * 128 + lane * 4) = hv;
    } else if (w < SEG + N_NODES) {
        int d = w - SEG;
        uint2 hv = reinterpret_cast<const uint2*>(XS + (size_t)d * 128)[lane];
        *reinterpret_cast<uint2*>(g_agg + (size_t)d * K_TOT + 1024 + lane * 4) = hv;
    }
}

// ---------------- B prep: single fp16 ----------------
template<int NB>
__global__ void prepB_kernel(const float* __restrict__ rel_w, const float* __restrict__ root_w,
                             __half* __restrict__ B)
{
    int i = blockIdx.x * blockDim.x + threadIdx.x;
    if (i >= 2 * NB * K_TOT) return;
    int k = i % K_TOT;
    int n = (i / K_TOT) % NB;
    int v = i / (K_TOT * NB);
    float w = (k < NT * 128) ? rel_w[(k >> 7) * NB * 128 + n * 128 + (k & 127)]
                             : root_w[v * NB * 128 + n * 128 + (k - NT * 128)];
    B[i] = __float2half_rn(w);
}

// ---------------- fp16 single-pass mma.sync GEMM, cp.async double buffered ----------------
// EPI 0: BN=128, ONE CTA per M-tile (A read once), relu(D+bias) -> fp16 out, grid (NTILES)
// EPI 1: BN=40, log_softmax(D+bias) -> fp32 out, grid (NTILES)
template<int BN, int EPI>
__global__ void __launch_bounds__(256, 2) gemm_kernel(
    const __half* __restrict__ B, const float* __restrict__ bias, void* __restrict__ outp_)
{
    constexpr int NBT = (EPI == 0) ? 128 : 40;
    constexpr int WARPS_M = (BN == 128) ? 4 : 8;
    constexpr int WARPS_N = (BN == 128) ? 2 : 1;
    constexpr int WM = 128 / WARPS_M;          // 32 or 16
    constexpr int WN = BN / WARPS_N;           // 64 or 40
    constexpr int MF = WM / 16;                // 2 or 1
    constexpr int NF = WN / 8;                 // 8 or 5
    constexpr int A_BYTES = 128 * KC * 2;      // 16384
    constexpr int B_BYTES = BN * KC * 2;
    constexpr int STAGE = A_BYTES + B_BYTES;

    extern __shared__ char smem[];
    const uint32_t sbase = smem_u32(smem);

    const int tid  = threadIdx.x;
    const int wid  = tid >> 5;
    const int lane = tid & 31;
    const int warpM = wid % WARPS_M;
    const int warpN = wid / WARPS_M;

    const int tile = blockIdx.x;
    const int var = (tile < TILES0) ? 0 : 1;
    const int mrow0 = var ? (N0 + (tile - TILES0) * 128) : (tile * 128);
    const int row_end = var ? N_NODES : N0;
    const __half* Bv = B + (size_t)var * NBT * K_TOT;
    const float* biasv = bias + var * NBT;
    const size_t aggRow0 = (size_t)mrow0 * K_TOT;

    float acc[MF][NF][4];
#pragma unroll
    for (int i = 0; i < MF; i++)
#pragma unroll
        for (int j = 0; j < NF; j++)
#pragma unroll
            for (int q = 0; q < 4; q++) acc[i][j][q] = 0.f;

    // ---- cp.async issue for chunk c into stage c&1 ----
    auto issue = [&](int c) {
        uint32_t ust = sbase + (c & 1) * STAGE;
        // A: 1024 x 16B
#pragma unroll
        for (int i = 0; i < 4; i++) {
            int idx = tid + i * 256;               // 0..1023
            int row = idx >> 3, u = idx & 7;
            const __half* gp = g_agg + aggRow0 + (size_t)row * K_TOT + c * KC + u * 8;
            cp16(ust + row * 128 + ((u ^ (row & 7)) << 4), gp);
        }
        // B: BN*8 x 16B
        constexpr int BITEMS = BN * 8;
#pragma unroll
        for (int j = 0; j < (BITEMS + 255) / 256; j++) {
            int idx = tid + j * 256;
            if ((BITEMS % 256 == 0) || idx < BITEMS) {
                int n = idx >> 3, u = idx & 7;
                const __half* gp = Bv + (size_t)n * K_TOT + c * KC + u * 8;
                cp16(ust + A_BYTES + n * 128 + ((u ^ (n & 7)) << 4), gp);
            }
        }
        cp_commit();
    };

    issue(0);
    for (int c = 0; c < NCHUNK; c++) {
        if (c + 1 < NCHUNK) { issue(c + 1); cp_wait<1>(); }
        else                { cp_wait<0>(); }
        __syncthreads();

        const uint32_t ust = sbase + (c & 1) * STAGE;
        const uint32_t uA  = ust;
        const uint32_t uB  = ust + A_BYTES;

#pragma unroll
        for (int ks = 0; ks < 4; ks++) {
            uint32_t a[MF][4];
#pragma unroll
            for (int mf = 0; mf < MF; mf++) {
                int row = warpM * WM + mf * 16 + (lane & 15);
                int u = 2 * ks + (lane >> 4);
                ldsm_x4(uA + row * 128 + ((u ^ (row & 7)) << 4), a[mf]);
            }
#pragma unroll
            for (int nfp = 0; nfp < NF / 2; nfp++) {
                int nrow = warpN * WN + nfp * 16 + ((lane >> 4) * 8) + (lane & 7);
                int u = 2 * ks + ((lane >> 3) & 1);
                uint32_t b[4];
                ldsm_x4(uB + nrow * 128 + ((u ^ (nrow & 7)) << 4), b);
#pragma unroll
                for (int mf = 0; mf < MF; mf++) {
                    mma_f16(acc[mf][2 * nfp + 0], a[mf], b[0], b[1]);
                    mma_f16(acc[mf][2 * nfp + 1], a[mf], b[2], b[3]);
                }
            }
            if (NF & 1) {
                int l = lane & 15;
                int nrow = warpN * WN + (NF - 1) * 8 + (l & 7);
                int u = 2 * ks + (l >> 3);
                uint32_t b[2];
                ldsm_x2(uB + nrow * 128 + ((u ^ (nrow & 7)) << 4), b);
#pragma unroll
                for (int mf = 0; mf < MF; mf++)
                    mma_f16(acc[mf][NF - 1], a[mf], b[0], b[1]);
            }
        }
        __syncthreads();
    }

    // ---- epilogue ----
    if (EPI == 0) {
        __half* outp = (__half*)outp_;
#pragma unroll
        for (int mf = 0; mf < MF; mf++) {
#pragma unroll
            for (int nf = 0; nf < NF; nf++) {
                int col = warpN * WN + nf * 8 + (lane & 3) * 2;
                float b0 = biasv[col], b1 = biasv[col + 1];
                int r0 = mrow0 + warpM * WM + mf * 16 + (lane >> 2);
                if (r0 < row_end) {
                    __half2 v = __floats2half2_rn(fmaxf(acc[mf][nf][0] + b0, 0.f),
                                                  fmaxf(acc[mf][nf][1] + b1, 0.f));
                    *reinterpret_cast<__half2*>(outp + (size_t)r0 * 128 + col) = v;
                }
                int r1 = r0 + 8;
                if (r1 < row_end) {
                    __half2 v = __floats2half2_rn(fmaxf(acc[mf][nf][2] + b0, 0.f),
                                                  fmaxf(acc[mf][nf][3] + b1, 0.f));
                    *reinterpret_cast<__half2*>(outp + (size_t)r1 * 128 + col) = v;
                }
            }
        }
    } else {
        float* outp = (float*)outp_;
#pragma unroll
        for (int h = 0; h < 2; h++) {
            int row = mrow0 + wid * 16 + (lane >> 2) + h * 8;
            float v[2 * NF];
            float m = -INFINITY;
#pragma unroll
            for (int f = 0; f < NF; f++) {
                int col = f * 8 + (lane & 3) * 2;
                v[2 * f + 0] = acc[0][f][2 * h + 0] + biasv[col];
                v[2 * f + 1] = acc[0][f][2 * h + 1] + biasv[col + 1];
                m = fmaxf(m, fmaxf(v[2 * f], v[2 * f + 1]));
            }
            m = fmaxf(m, __shfl_xor_sync(0xFFFFFFFFu, m, 1));
            m = fmaxf(m, __shfl_xor_sync(0xFFFFFFFFu, m, 2));
            float s = 0.f;
#pragma unroll
            for (int j = 0; j < 2 * NF; j++) s += expf(v[j] - m);
            s += __shfl_xor_sync(0xFFFFFFFFu, s, 1);
            s += __shfl_xor_sync(0xFFFFFFFFu, s, 2);
            float l = m + logf(s);
            if (row < row_end) {
#pragma unroll
                for (int f = 0; f < NF; f++) {
                    int col = f * 8 + (lane & 3) * 2;
                    float2 o = make_float2(v[2 * f] - l, v[2 * f + 1] - l);
                    *reinterpret_cast<float2*>(outp + (size_t)row * 40 + col) = o;
                }
            }
        }
    }
}

// ---------------- launch ----------------
extern "C" void kernel_launch(void* const* d_in, const int* in_sizes, int n_in,
                              void* d_out, int out_size)
{
    const float* x0      = (const float*)d_in[0];
    const float* emb1    = (const float*)d_in[1];
    const float* rel_w1  = (const float*)d_in[2];
    const float* root_w1 = (const float*)d_in[3];
    const float* root_b1 = (const float*)d_in[4];
    const float* rel_w2  = (const float*)d_in[5];
    const float* root_w2 = (const float*)d_in[6];
    const float* root_b2 = (const float*)d_in[7];
    const int*   eidx    = (const int*)d_in[8];
    const int*   etype   = (const int*)d_in[9];
    (void)in_sizes; (void)n_in; (void)out_size;

    const int* src = eidx;
    const int* dst = eidx + N_EDGES;
    float* out = (float*)d_out;

    void *p_cnt, *p_h1r, *p_B1, *p_B2;
    cudaGetSymbolAddress(&p_cnt, g_cnt);
    cudaGetSymbolAddress(&p_h1r, g_h1r);
    cudaGetSymbolAddress(&p_B1, g_B1);
    cudaGetSymbolAddress(&p_B2, g_B2);

    constexpr int SMEM1 = 2 * (128 * KC * 2 + 128 * KC * 2);  // 65536
    constexpr int SMEM2 = 2 * (128 * KC * 2 + 40 * KC * 2);   // 43008
    cudaFuncSetAttribute(gemm_kernel<128, 0>, cudaFuncAttributeMaxDynamicSharedMemorySize, SMEM1);
    cudaFuncSetAttribute(gemm_kernel<40, 1>,  cudaFuncAttributeMaxDynamicSharedMemorySize, SMEM2);

    // input fp16 conversion + B weight conversion (tiny)
    convx_kernel<<<(N_NODES * 32 + 255) / 256, 256>>>(x0, emb1);
    prepB_kernel<128><<<(2 * 128 * K_TOT + 255) / 256, 256>>>(rel_w1, root_w1, (__half*)p_B1);
    prepB_kernel<40><<<(2 * 40 * K_TOT + 255) / 256, 256>>>(rel_w2, root_w2, (__half*)p_B2);

    // CSR build: count -> scan -> scatter
    cudaMemsetAsync(p_cnt, 0, sizeof(int) * SEG);
    count_kernel<<<(N_EDGES + 255) / 256, 256>>>(dst, etype);
    scanA_kernel<<<NBLK, 256>>>();
    scanB_kernel<<<1, 512>>>();
    scanC_kernel<<<NBLK, 256>>>();
    scatter_kernel<<<(N_EDGES + 255) / 256, 256>>>(src, dst, etype);

    const int AGG_BLOCKS = ((SEG + N_NODES) * 32 + 255) / 256;

    // layer 1: aggregation (fp16 gathers, skip-empty, +root fill) + GEMM -> g_h1r (fp16)
    agg_kernel<0><<<AGG_BLOCKS, 256>>>();
    gemm_kernel<128, 0><<<NTILES, 256, SMEM1>>>((const __half*)p_B1, root_b1, p_h1r);

    // layer 2: aggregation (fp16 gathers, skip-empty) + GEMM -> d_out
    agg_kernel<1><<<AGG_BLOCKS, 256>>>();
    gemm_kernel<40, 1><<<NTILES, 256, SMEM2>>>((const __half*)p_B2, root_b2, out);
}